// round 6
// baseline (speedup 1.0000x reference)
#include <cuda_runtime.h>

// ---------------------------------------------------------------------------
// Problem constants (fixed shapes from setup_inputs)
//   B=4, C=256, levels: 16x16 -> 32x32 -> 64x64 -> 128x128, dg=8, Cpg=32
// ---------------------------------------------------------------------------
#define NB 4

// ------------------------- static scratch buffers --------------------------
static __device__ float g_up5 [4u * 256u * 32u * 32u];
static __device__ float g_off5[4u * 256u * 32u * 32u];
static __device__ float g_om5 [4u * 216u * 32u * 32u];
static __device__ float g_col [4u * 2304u * 64u * 64u];   // 151 MB (shared by both DCN levels)
static __device__ float g_al5 [4u * 256u * 32u * 32u];
static __device__ float g_c1b [4u * 256u * 32u * 32u];
static __device__ float g_up4 [4u * 256u * 64u * 64u];
static __device__ float g_off4[4u * 256u * 64u * 64u];
static __device__ float g_om4 [4u * 216u * 64u * 64u];
static __device__ float g_al4 [4u * 256u * 64u * 64u];
static __device__ float g_f2  [4u * 512u * 128u * 128u];
static __device__ float g_mm  [4u * 2u * 128u * 128u];
static __device__ float g_sab [4u * 128u * 128u];
static __device__ float g_y   [4u * 256u * 128u * 128u];
static __device__ float g_st  [256];

// ---------------------------------------------------------------------------
// Bilinear 2x upsample, half-pixel centers, clamp-to-edge.
// Dual source: channel c < Csplit reads src0, else src1 (fuses concat+resize).
// ---------------------------------------------------------------------------
__global__ __launch_bounds__(256)
void upsample2x_kernel(const float* __restrict__ src0,
                       const float* __restrict__ src1,
                       int Csplit, int C, int Hin, int Win,
                       float* __restrict__ dst)
{
    const int Hout = Hin * 2, Wout = Win * 2;
    const long total = (long)NB * C * Hout * Wout;
    long idx = (long)blockIdx.x * blockDim.x + threadIdx.x;
    if (idx >= total) return;
    int x = (int)(idx % Wout);
    int y = (int)((idx / Wout) % Hout);
    int c = (int)((idx / ((long)Wout * Hout)) % C);
    int b = (int)(idx / ((long)Wout * Hout * C));

    float sy = y * 0.5f - 0.25f;
    float sx = x * 0.5f - 0.25f;
    float y0f = floorf(sy), x0f = floorf(sx);
    float fy = sy - y0f, fx = sx - x0f;
    int y0 = (int)y0f, x0 = (int)x0f;
    int y0c = min(max(y0, 0), Hin - 1);
    int y1c = min(max(y0 + 1, 0), Hin - 1);
    int x0c = min(max(x0, 0), Win - 1);
    int x1c = min(max(x0 + 1, 0), Win - 1);

    const float* s = (c < Csplit)
        ? src0 + (size_t)(b * Csplit + c) * Hin * Win
        : src1 + (size_t)(b * (C - Csplit) + (c - Csplit)) * Hin * Win;

    float v00 = s[y0c * Win + x0c];
    float v01 = s[y0c * Win + x1c];
    float v10 = s[y1c * Win + x0c];
    float v11 = s[y1c * Win + x1c];
    dst[idx] = (1.f - fy) * ((1.f - fx) * v00 + fx * v01)
             +         fy * ((1.f - fx) * v10 + fx * v11);
}

// ---------------------------------------------------------------------------
// X loader modes (shared by GEMM):
//   0: plain         X0 is [B][K][N]
//   1: concat        k<Csplit -> X0[B][Csplit][N] ; else scale1 * X1[...]
//   2: im2col 3x3    X0 is [B][K/9][Hin][Win]; zero pad=1
//   3: sa-scaled     X0[B][K][N] * (1 + sa[B][N])
// ---------------------------------------------------------------------------
template<int MODE>
__device__ __forceinline__ float loadX(const float* __restrict__ X0,
                                       const float* __restrict__ X1,
                                       const float* __restrict__ sa,
                                       int b, int k, int p,
                                       int K, int N, int Csplit, float scale1,
                                       int Hin, int Win)
{
    if (MODE == 0) {
        return X0[((size_t)b * K + k) * N + p];
    } else if (MODE == 1) {
        if (k < Csplit)
            return X0[((size_t)b * Csplit + k) * N + p];
        return scale1 * X1[((size_t)b * (K - Csplit) + (k - Csplit)) * N + p];
    } else if (MODE == 2) {
        int cin = k / 9;
        int t   = k - cin * 9;
        int hh  = p / Win + (t / 3) - 1;
        int ww  = (p - (p / Win) * Win) + (t - (t / 3) * 3) - 1;
        if ((unsigned)hh < (unsigned)Hin && (unsigned)ww < (unsigned)Win)
            return X0[(((size_t)b * (K / 9) + cin) * Hin + hh) * Win + ww];
        return 0.f;
    } else { // MODE 3
        return X0[((size_t)b * K + k) * N + p] * (1.f + sa[(size_t)b * N + p]);
    }
}

// ---------------------------------------------------------------------------
// Packed-f32x2 GEMM: out[b, m, p] = act( sum_k W[m,k] * X(b,k,p) + bias[m] )
// BM=128, BN = 64 or 128, BK=16, 256 threads, microtile 8 x (BN/16).
// Uses SASS FFMA2 via PTX fma.rn.f32x2 (2x fp32 FMA throughput).
//  - A stored DUPLICATED in SMEM ((a,a) per element): one broadcast LDS.128
//    yields two 64-bit duplicated A operands -> no packing MOVs.
//  - X pairs come naturally from a conflict-free LDS.128 of plain Xs.
// ---------------------------------------------------------------------------
#define FMA2(c, a, b) asm("fma.rn.f32x2 %0, %1, %2, %0;" : "+l"(c) : "l"(a), "l"(b))

union F4U {
    float4 f;
    unsigned long long u[2];
    float s[4];
};

template<int MODE, int BN>
__global__ __launch_bounds__(256, 2)
void gemm2_kernel(const float* __restrict__ Wt,
                  const float* __restrict__ X0,
                  const float* __restrict__ X1,
                  const float* __restrict__ bias,
                  const float* __restrict__ sa,
                  float* __restrict__ out,
                  int M, int K, int N, int Csplit, float scale1,
                  int Hin, int Win, int relu)
{
    constexpr int AS_STRIDE = 260;          // 128*2 + 4 pad (keeps 16B align, spreads banks)
    constexpr int NJ = BN / 64;             // float4 X loads per kk (1 or 2)
    __shared__ __align__(16) float As2[16 * AS_STRIDE];
    __shared__ __align__(16) float Xs[16 * BN];

    const int n0  = blockIdx.x * BN;
    const int m0  = blockIdx.y * 128;
    const int b   = blockIdx.z;
    const int tid = threadIdx.x;
    const int tx  = tid & 15;               // n quad
    const int ty  = tid >> 4;               // m oct

    unsigned long long acc[8][2 * NJ];
#pragma unroll
    for (int i = 0; i < 8; i++)
#pragma unroll
        for (int j = 0; j < 2 * NJ; j++) acc[i][j] = 0ull;  // packed (0.f, 0.f)

    for (int k0 = 0; k0 < K; k0 += 16) {
        // ---- fill A tile (128 m x 16 k), duplicated, coalesced W reads ----
#pragma unroll
        for (int r = 0; r < 8; r++) {
            int i = tid + r * 256;
            int kk = i & 15, m = i >> 4;
            int row = m0 + m;
            float v = (row < M) ? Wt[(size_t)row * K + (k0 + kk)] : 0.f;
            *reinterpret_cast<float2*>(&As2[kk * AS_STRIDE + m * 2]) = make_float2(v, v);
        }
        // ---- fill X tile (16 k x BN n) ----
#pragma unroll
        for (int r = 0; r < (16 * BN) / 256; r++) {
            int i = tid + r * 256;
            int n = i & (BN - 1), kk = i / BN;
            Xs[kk * BN + n] = loadX<MODE>(X0, X1, sa, b, k0 + kk, n0 + n,
                                          K, N, Csplit, scale1, Hin, Win);
        }
        __syncthreads();

#pragma unroll
        for (int kk = 0; kk < 16; kk++) {
            unsigned long long xv[2 * NJ];
#pragma unroll
            for (int j = 0; j < NJ; j++) {
                F4U xu;
                xu.f = *reinterpret_cast<const float4*>(&Xs[kk * BN + j * 64 + tx * 4]);
                xv[2 * j]     = xu.u[0];
                xv[2 * j + 1] = xu.u[1];
            }
#pragma unroll
            for (int i2 = 0; i2 < 4; i2++) {
                F4U au;   // two duplicated A operands: (a[2i2],a[2i2]), (a[2i2+1],a[2i2+1])
                au.f = *reinterpret_cast<const float4*>(
                           &As2[kk * AS_STRIDE + (ty * 8 + i2 * 2) * 2]);
#pragma unroll
                for (int jj = 0; jj < 2 * NJ; jj++) {
                    FMA2(acc[i2 * 2][jj],     au.u[0], xv[jj]);
                    FMA2(acc[i2 * 2 + 1][jj], au.u[1], xv[jj]);
                }
            }
        }
        __syncthreads();
    }

    // ---- epilogue: bias + optional relu, float4 stores ----
#pragma unroll
    for (int i = 0; i < 8; i++) {
        int row = m0 + ty * 8 + i;
        if (row >= M) continue;
        float bv = bias ? bias[row] : 0.f;
#pragma unroll
        for (int j = 0; j < NJ; j++) {
            F4U o;
            o.u[0] = acc[i][2 * j];
            o.u[1] = acc[i][2 * j + 1];
#pragma unroll
            for (int q = 0; q < 4; q++) {
                float v = o.s[q] + bv;
                if (relu) v = fmaxf(v, 0.f);
                o.s[q] = v;
            }
            *reinterpret_cast<float4*>(
                &out[((size_t)b * M + row) * N + n0 + j * 64 + tx * 4]) = o.f;
        }
    }
}

// ---------------------------------------------------------------------------
// DCNv2 sampling -> im2col buffer col[b][(cin*9+k)][p], modulated bilinear,
// zero padding. One thread per (b,g,k,h,w); loops the group's 32 channels.
// ---------------------------------------------------------------------------
__global__ __launch_bounds__(256)
void dcn_sample_kernel(const float* __restrict__ x,
                       const float* __restrict__ om,
                       float* __restrict__ col,
                       int H, int W)
{
    const int HW = H * W;
    const int total = NB * 72 * HW;
    int idx = blockIdx.x * blockDim.x + threadIdx.x;
    if (idx >= total) return;

    int p  = idx % HW;
    int gk = (idx / HW) % 72;
    int b  = idx / (72 * HW);
    int g  = gk / 9, k = gk - g * 9;
    int h  = p / W, w = p - h * W;

    float offy = om[((size_t)b * 216 +        gk) * HW + p];
    float offx = om[((size_t)b * 216 +  72 +  gk) * HW + p];
    float mraw = om[((size_t)b * 216 + 144 +  gk) * HW + p];
    float msk  = 1.f / (1.f + expf(-mraw));

    float yy = (float)h + (float)(k / 3 - 1) + offy;
    float xx = (float)w + (float)(k % 3 - 1) + offx;
    yy = fminf(fmaxf(yy, -1.0e6f), 1.0e6f);
    xx = fminf(fmaxf(xx, -1.0e6f), 1.0e6f);

    float y0f = floorf(yy), x0f = floorf(xx);
    int y0 = (int)y0f, x0 = (int)x0f;
    float fy = yy - y0f, fx = xx - x0f;

    bool vy0 = (y0 >= 0) && (y0 < H);
    bool vy1 = (y0 + 1 >= 0) && (y0 + 1 < H);
    bool vx0 = (x0 >= 0) && (x0 < W);
    bool vx1 = (x0 + 1 >= 0) && (x0 + 1 < W);

    int cy0 = min(max(y0, 0), H - 1);
    int cy1 = min(max(y0 + 1, 0), H - 1);
    int cx0 = min(max(x0, 0), W - 1);
    int cx1 = min(max(x0 + 1, 0), W - 1);

    float w00 = (vy0 && vx0) ? (1.f - fy) * (1.f - fx) * msk : 0.f;
    float w01 = (vy0 && vx1) ? (1.f - fy) * fx * msk : 0.f;
    float w10 = (vy1 && vx0) ? fy * (1.f - fx) * msk : 0.f;
    float w11 = (vy1 && vx1) ? fy * fx * msk : 0.f;

    int i00 = cy0 * W + cx0, i01 = cy0 * W + cx1;
    int i10 = cy1 * W + cx0, i11 = cy1 * W + cx1;

    const float* xb = x + (size_t)(b * 256 + g * 32) * HW;
    float* cb = col + ((size_t)b * 2304 + (size_t)(g * 32) * 9 + k) * HW + p;

#pragma unroll 4
    for (int c = 0; c < 32; c++) {
        const float* xc = xb + (size_t)c * HW;
        float v = w00 * xc[i00] + w01 * xc[i01] + w10 * xc[i10] + w11 * xc[i11];
        cb[(size_t)c * 9 * HW] = v;
    }
}

// ---------------------------------------------------------------------------
// Channel mean + max over 512 channels at 128x128 (sem front-end).
// ---------------------------------------------------------------------------
__global__ __launch_bounds__(256)
void meanmax_kernel(const float* __restrict__ f2, float* __restrict__ mm)
{
    int p = blockIdx.x * blockDim.x + threadIdx.x;
    int b = blockIdx.y;
    if (p >= 16384) return;
    const float* base = f2 + (size_t)b * 512 * 16384 + p;
    float s = 0.f, mx = -3.402823466e38f;
    for (int c = 0; c < 512; c++) {
        float v = base[(size_t)c * 16384];
        s += v;
        mx = fmaxf(mx, v);
    }
    mm[((size_t)b * 2 + 0) * 16384 + p] = s * (1.f / 512.f);
    mm[((size_t)b * 2 + 1) * 16384 + p] = mx;
}

// ---------------------------------------------------------------------------
// 7x7 conv (2 -> 1, pad 3) + BatchNorm (inference) + sigmoid -> sa[b][p]
// ---------------------------------------------------------------------------
__global__ __launch_bounds__(256)
void sa_kernel(const float* __restrict__ mm, const float* __restrict__ wsa,
               const float* __restrict__ bng, const float* __restrict__ bnb,
               const float* __restrict__ bnm, const float* __restrict__ bnv,
               float* __restrict__ sa)
{
    int p = blockIdx.x * blockDim.x + threadIdx.x;
    int b = blockIdx.y;
    if (p >= 16384) return;
    int y = p >> 7, x = p & 127;
    float acc = 0.f;
#pragma unroll
    for (int ic = 0; ic < 2; ic++) {
        const float* src = mm + ((size_t)b * 2 + ic) * 16384;
        const float* wk = wsa + ic * 49;
#pragma unroll
        for (int ky = 0; ky < 7; ky++) {
            int yy = y + ky - 3;
            if ((unsigned)yy >= 128u) continue;
#pragma unroll
            for (int kx = 0; kx < 7; kx++) {
                int xx = x + kx - 3;
                if ((unsigned)xx >= 128u) continue;
                acc += src[yy * 128 + xx] * wk[ky * 7 + kx];
            }
        }
    }
    float a = (acc - bnm[0]) * rsqrtf(bnv[0] + 1e-5f) * bng[0] + bnb[0];
    sa[(size_t)b * 16384 + p] = 1.f / (1.f + expf(-a));
}

// ---------------------------------------------------------------------------
// GroupNorm (32 groups over C=256, HW=16384). Reduce then apply.
// ---------------------------------------------------------------------------
__global__ __launch_bounds__(256)
void gn_reduce_kernel(const float* __restrict__ y, float* __restrict__ stats)
{
    const int bg = blockIdx.x;
    const float* base = y + (size_t)bg * 8 * 16384;
    float s = 0.f, sq = 0.f;
    for (int i = threadIdx.x; i < 8 * 16384; i += 256) {
        float v = base[i];
        s += v;
        sq += v * v;
    }
    __shared__ float ss[256], ssq[256];
    ss[threadIdx.x] = s;
    ssq[threadIdx.x] = sq;
    __syncthreads();
    for (int st = 128; st > 0; st >>= 1) {
        if (threadIdx.x < st) {
            ss[threadIdx.x]  += ss[threadIdx.x + st];
            ssq[threadIdx.x] += ssq[threadIdx.x + st];
        }
        __syncthreads();
    }
    if (threadIdx.x == 0) {
        const float inv = 1.f / (8.f * 16384.f);
        float mean = ss[0] * inv;
        float var  = ssq[0] * inv - mean * mean;
        stats[bg * 2 + 0] = mean;
        stats[bg * 2 + 1] = rsqrtf(var + 1e-5f);
    }
}

__global__ __launch_bounds__(256)
void gn_apply_kernel(const float* __restrict__ y, const float* __restrict__ stats,
                     const float* __restrict__ gg, const float* __restrict__ gb,
                     float* __restrict__ out)
{
    size_t idx = (size_t)blockIdx.x * blockDim.x + threadIdx.x;
    if (idx >= (size_t)16777216) return;
    int c = (int)((idx >> 14) & 255);
    int b = (int)(idx >> 22);
    int g = c >> 3;
    float mean = stats[(b * 32 + g) * 2 + 0];
    float rstd = stats[(b * 32 + g) * 2 + 1];
    out[idx] = (y[idx] - mean) * rstd * gg[c] + gb[c];
}

// ---------------------------------------------------------------------------
// Host orchestration
// ---------------------------------------------------------------------------
static void* symaddr(const void* sym)
{
    void* p = nullptr;
    cudaGetSymbolAddress(&p, sym);
    return p;
}

extern "C" void kernel_launch(void* const* d_in, const int* in_sizes, int n_in,
                              void* d_out, int out_size)
{
    (void)in_sizes; (void)n_in; (void)out_size;

    const float* feat_3 = (const float*)d_in[1];
    const float* feat_4 = (const float*)d_in[2];
    const float* feat_5 = (const float*)d_in[3];
    const float* w_off5 = (const float*)d_in[4];
    const float* w_om5  = (const float*)d_in[5];
    const float* b_om5  = (const float*)d_in[6];
    const float* w_dcn5 = (const float*)d_in[7];
    const float* b_dcn5 = (const float*)d_in[8];
    const float* w_c1   = (const float*)d_in[9];
    const float* w_off4 = (const float*)d_in[10];
    const float* w_om4  = (const float*)d_in[11];
    const float* b_om4  = (const float*)d_in[12];
    const float* w_dcn4 = (const float*)d_in[13];
    const float* b_dcn4 = (const float*)d_in[14];
    const float* w_sa   = (const float*)d_in[15];
    const float* bn_g   = (const float*)d_in[16];
    const float* bn_b   = (const float*)d_in[17];
    const float* bn_m   = (const float*)d_in[18];
    const float* bn_v   = (const float*)d_in[19];
    const float* w_sem  = (const float*)d_in[20];
    const float* gn_g   = (const float*)d_in[21];
    const float* gn_b   = (const float*)d_in[22];
    float* out = (float*)d_out;

    float* up5  = (float*)symaddr(g_up5);
    float* off5 = (float*)symaddr(g_off5);
    float* om5  = (float*)symaddr(g_om5);
    float* col  = (float*)symaddr(g_col);
    float* al5  = (float*)symaddr(g_al5);
    float* c1b  = (float*)symaddr(g_c1b);
    float* up4  = (float*)symaddr(g_up4);
    float* off4 = (float*)symaddr(g_off4);
    float* om4  = (float*)symaddr(g_om4);
    float* al4  = (float*)symaddr(g_al4);
    float* f2   = (float*)symaddr(g_f2);
    float* mm   = (float*)symaddr(g_mm);
    float* sab  = (float*)symaddr(g_sab);
    float* ybuf = (float*)symaddr(g_y);
    float* st   = (float*)symaddr(g_st);

    // ----- level 5 (16 -> 32), N=1024: BN=64 to fill the chip ---------------
    {
        long total = 4L * 256 * 32 * 32;
        upsample2x_kernel<<<(unsigned)((total + 255) / 256), 256>>>(
            feat_5, feat_5, 256, 256, 16, 16, up5);
    }
    // off5 = conv1x1(concat(feat_4, 2*feat_up5))
    gemm2_kernel<1, 64><<<dim3(1024 / 64, 2, NB), 256>>>(
        w_off5, feat_4, up5, nullptr, nullptr, off5,
        256, 512, 1024, 256, 2.0f, 0, 0, 0);
    // om5 = conv3x3(off5) + b_om5   (implicit im2col GEMM)
    gemm2_kernel<2, 64><<<dim3(1024 / 64, 2, NB), 256>>>(
        w_om5, off5, nullptr, b_om5, nullptr, om5,
        216, 2304, 1024, 0, 0.f, 32, 32, 0);
    // DCN sampling -> col
    {
        int total = NB * 72 * 1024;
        dcn_sample_kernel<<<(total + 255) / 256, 256>>>(up5, om5, col, 32, 32);
    }
    // feat_5_align = relu(W_dcn5 * col + b)
    gemm2_kernel<0, 64><<<dim3(1024 / 64, 2, NB), 256>>>(
        w_dcn5, col, nullptr, b_dcn5, nullptr, al5,
        256, 2304, 1024, 0, 0.f, 0, 0, 1);
    // feat_4' = conv1x1(concat(feat_5_align, feat_4))
    gemm2_kernel<1, 64><<<dim3(1024 / 64, 2, NB), 256>>>(
        w_c1, al5, feat_4, nullptr, nullptr, c1b,
        256, 512, 1024, 256, 1.0f, 0, 0, 0);

    // ----- level 4 (32 -> 64), N=4096: BN=128 --------------------------------
    {
        long total = 4L * 256 * 64 * 64;
        upsample2x_kernel<<<(unsigned)((total + 255) / 256), 256>>>(
            c1b, c1b, 256, 256, 32, 32, up4);
    }
    gemm2_kernel<1, 128><<<dim3(4096 / 128, 2, NB), 256>>>(
        w_off4, feat_3, up4, nullptr, nullptr, off4,
        256, 512, 4096, 256, 2.0f, 0, 0, 0);
    gemm2_kernel<2, 128><<<dim3(4096 / 128, 2, NB), 256>>>(
        w_om4, off4, nullptr, b_om4, nullptr, om4,
        216, 2304, 4096, 0, 0.f, 64, 64, 0);
    {
        int total = NB * 72 * 4096;
        dcn_sample_kernel<<<(total + 255) / 256, 256>>>(up4, om4, col, 64, 64);
    }
    gemm2_kernel<0, 128><<<dim3(4096 / 128, 2, NB), 256>>>(
        w_dcn4, col, nullptr, b_dcn4, nullptr, al4,
        256, 2304, 4096, 0, 0.f, 0, 0, 1);

    // ----- feat_2 = resize(concat(feat_4_align, feat_3), 128x128) ------------
    {
        long total = 4L * 512 * 128 * 128;
        upsample2x_kernel<<<(unsigned)((total + 255) / 256), 256>>>(
            al4, feat_3, 256, 512, 64, 64, f2);
    }

    // ----- SEM ---------------------------------------------------------------
    meanmax_kernel<<<dim3(16384 / 256, NB), 256>>>(f2, mm);
    sa_kernel<<<dim3(16384 / 256, NB), 256>>>(mm, w_sa, bn_g, bn_b, bn_m, bn_v, sab);
    // y = conv1x1( feat_2 * (1 + sa) )   [fused spatial attention]
    gemm2_kernel<3, 128><<<dim3(16384 / 128, 2, NB), 256>>>(
        w_sem, f2, nullptr, nullptr, sab, ybuf,
        256, 512, 16384, 0, 0.f, 0, 0, 0);
    // GroupNorm
    gn_reduce_kernel<<<128, 256>>>(ybuf, st);
    gn_apply_kernel<<<16777216 / 256, 256>>>(ybuf, st, gn_g, gn_b, out);
}

// round 11
// speedup vs baseline: 1.1513x; 1.1513x over previous
#include <cuda_runtime.h>
#include <cuda_bf16.h>
#include <cstdint>

#define NB 4

// ------------------------- static scratch buffers --------------------------
static __device__ float g_up5 [4u * 256u * 32u * 32u];
static __device__ float g_off5[4u * 256u * 32u * 32u];
static __device__ float g_om5 [4u * 216u * 32u * 32u];
static __device__ float g_col [4u * 2304u * 64u * 64u];
static __device__ float g_al5 [4u * 256u * 32u * 32u];
static __device__ float g_c1b [4u * 256u * 32u * 32u];
static __device__ float g_up4 [4u * 256u * 64u * 64u];
static __device__ float g_off4[4u * 256u * 64u * 64u];
static __device__ float g_om4 [4u * 216u * 64u * 64u];
static __device__ float g_al4 [4u * 256u * 64u * 64u];
static __device__ float g_f2  [4u * 512u * 128u * 128u];
static __device__ float g_mm  [4u * 2u * 128u * 128u];
static __device__ float g_sab [4u * 128u * 128u];
static __device__ float g_y   [4u * 256u * 128u * 128u];
static __device__ float g_st  [256];
// pre-split weights: [hi(256*K) | lo(256*K)] bf16, M zero-padded to 256
static __device__ __align__(16) __nv_bfloat16 g_wp[5767168];
#define WP_OFF5 0u
#define WP_OM5  262144u
#define WP_DCN5 1441792u
#define WP_C1   2621440u
#define WP_OFF4 2883584u
#define WP_OM4  3145728u
#define WP_DCN4 4325376u
#define WP_SEM  5505024u

// ---------------------------------------------------------------------------
// Weight prep: W[M][K] fp32 -> out[0..256*K) = hi bf16, out[256*K..) = lo bf16
// ---------------------------------------------------------------------------
__global__ __launch_bounds__(256)
void prep_w_kernel(const float* __restrict__ W, __nv_bfloat16* __restrict__ out,
                   int M, int K)
{
    int idx = blockIdx.x * 256 + threadIdx.x;
    if (idx >= 256 * K) return;
    int m = idx / K, k = idx - m * K;
    float v = (m < M) ? W[(size_t)m * K + k] : 0.f;
    __nv_bfloat16 hi = __float2bfloat16(v);
    __nv_bfloat16 lo = __float2bfloat16(v - __bfloat162float(hi));
    out[idx] = hi;
    out[(size_t)256 * K + idx] = lo;
}

// X loader modes: 0 plain [K][N], 1 concat(+scale), 2 im2col3x3 pad1, 3 (1+sa)
template<int MODE>
__device__ __forceinline__ float loadX(const float* __restrict__ X0,
                                       const float* __restrict__ X1,
                                       const float* __restrict__ sa,
                                       int b, int k, int p,
                                       int K, int N, int Csplit, float scale1,
                                       int Hin, int Win)
{
    if (MODE == 0) return X0[((size_t)b * K + k) * N + p];
    else if (MODE == 1) {
        if (k < Csplit) return X0[((size_t)b * Csplit + k) * N + p];
        return scale1 * X1[((size_t)b * (K - Csplit) + (k - Csplit)) * N + p];
    } else if (MODE == 2) {
        int cin = k / 9, t = k - cin * 9;
        int hh = p / Win + (t / 3) - 1;
        int ww = (p - (p / Win) * Win) + (t - (t / 3) * 3) - 1;
        if ((unsigned)hh < (unsigned)Hin && (unsigned)ww < (unsigned)Win)
            return X0[(((size_t)b * (K / 9) + cin) * Hin + hh) * Win + ww];
        return 0.f;
    } else return X0[((size_t)b * K + k) * N + p] * (1.f + sa[(size_t)b * N + p]);
}

__device__ __forceinline__ void mma_bf16(float* c, const unsigned* a, const unsigned* b)
{
    asm volatile(
        "mma.sync.aligned.m16n8k16.row.col.f32.bf16.bf16.f32 "
        "{%0,%1,%2,%3}, {%4,%5,%6,%7}, {%8,%9}, {%0,%1,%2,%3};"
        : "+f"(c[0]), "+f"(c[1]), "+f"(c[2]), "+f"(c[3])
        : "r"(a[0]), "r"(a[1]), "r"(a[2]), "r"(a[3]), "r"(b[0]), "r"(b[1]));
}

// ---------------------------------------------------------------------------
// mma.sync bf16 split GEMM: out[b,m,n] = act( sum_k W[m,k] X(b,k,n) + bias[m] )
// Block 128(M) x 128(N), BK=32, 256 threads (8 warps: 4 M-warps x 2 N-warps).
// Warp tile 32x64 -> mma grid 2(i) x 8(j) of m16n8k16.
// Split: acc += Ah*Xh + Ah*Xl + Al*Xh  (fp32 accumulators).
// SMEM: Ah[128][72]bf16, Al same; Xh[128(n)][40(k)]bf16, Xl same. 57344 B.
// ---------------------------------------------------------------------------
#define SA32 36   // A row stride in b32 units (72 bf16)
#define SX32 20   // X row stride in b32 units (40 bf16)
#define OFF_AL 18432
#define OFF_XH 36864
#define OFF_XL 47104
#define SMEM_DYN 57344

template<int MODE>
__global__ __launch_bounds__(256, 2)
void gemm_mma_kernel(const __nv_bfloat16* __restrict__ Wp,
                     const float* __restrict__ X0, const float* __restrict__ X1,
                     const float* __restrict__ bias, const float* __restrict__ sa,
                     float* __restrict__ out,
                     int M, int K, int N, int Csplit, float scale1,
                     int Hin, int Win, int relu)
{
    extern __shared__ char smem[];
    unsigned* Ah32 = (unsigned*)smem;
    unsigned* Al32 = (unsigned*)(smem + OFF_AL);
    unsigned* Xh32 = (unsigned*)(smem + OFF_XH);
    unsigned* Xl32 = (unsigned*)(smem + OFF_XL);
    __nv_bfloat16* XhE = (__nv_bfloat16*)(smem + OFF_XH);
    __nv_bfloat16* XlE = (__nv_bfloat16*)(smem + OFF_XL);

    const int tid = threadIdx.x;
    const int wid = tid >> 5, lane = tid & 31;
    const int warp_m = wid & 3;          // 0..3 -> 32 rows each
    const int warp_n = wid >> 2;         // 0..1 -> 64 cols each
    const int lq = lane >> 2;            // row-in-8 group
    const int lr = lane & 3;             // k pair
    const int m0 = blockIdx.y * 128;
    const int n0 = blockIdx.x * 128;
    const int b  = blockIdx.z;

    float acc[2][8][4];
#pragma unroll
    for (int i = 0; i < 2; i++)
#pragma unroll
        for (int j = 0; j < 8; j++)
#pragma unroll
            for (int q = 0; q < 4; q++) acc[i][j][q] = 0.f;

    const size_t loStride = (size_t)256 * K;   // lo plane offset in Wp

    for (int k0 = 0; k0 < K; k0 += 32) {
        // ---- fill A: 128 rows x 16 b32 (hi & lo) ----
#pragma unroll
        for (int r = 0; r < 8; r++) {
            int i = tid + r * 256;             // 0..2047
            int m = i >> 4, kp = i & 15;
            const unsigned* gh = (const unsigned*)(Wp + (size_t)(m0 + m) * K + k0);
            const unsigned* gl = (const unsigned*)(Wp + loStride + (size_t)(m0 + m) * K + k0);
            Ah32[m * SA32 + kp] = gh[kp];
            Al32[m * SA32 + kp] = gl[kp];
        }
        // ---- fill X: 32 k x 128 n, split, store [n][k] ----
#pragma unroll
        for (int r = 0; r < 16; r++) {
            int i = tid + r * 256;             // 0..4095
            int n = i & 127, k = i >> 7;
            float v = loadX<MODE>(X0, X1, sa, b, k0 + k, n0 + n,
                                  K, N, Csplit, scale1, Hin, Win);
            __nv_bfloat16 h = __float2bfloat16(v);
            __nv_bfloat16 l = __float2bfloat16(v - __bfloat162float(h));
            XhE[n * 40 + k] = h;
            XlE[n * 40 + k] = l;
        }
        __syncthreads();

#pragma unroll
        for (int ks = 0; ks < 2; ks++) {
            const int kb = ks * 8 + lr;        // b32 index within row
            unsigned ah[2][4], al[2][4];
#pragma unroll
            for (int i = 0; i < 2; i++) {
                int mt = warp_m * 32 + i * 16;
                int r0 = (mt + lq) * SA32, r1 = (mt + lq + 8) * SA32;
                ah[i][0] = Ah32[r0 + kb];
                ah[i][1] = Ah32[r1 + kb];
                ah[i][2] = Ah32[r0 + kb + 4];
                ah[i][3] = Ah32[r1 + kb + 4];
                al[i][0] = Al32[r0 + kb];
                al[i][1] = Al32[r1 + kb];
                al[i][2] = Al32[r0 + kb + 4];
                al[i][3] = Al32[r1 + kb + 4];
            }
#pragma unroll
            for (int j = 0; j < 8; j++) {
                int nr = (warp_n * 64 + j * 8 + lq) * SX32;
                unsigned bh[2], bl[2];
                bh[0] = Xh32[nr + kb];
                bh[1] = Xh32[nr + kb + 4];
                bl[0] = Xl32[nr + kb];
                bl[1] = Xl32[nr + kb + 4];
#pragma unroll
                for (int i = 0; i < 2; i++) {
                    mma_bf16(acc[i][j], ah[i], bh);
                    mma_bf16(acc[i][j], ah[i], bl);
                    mma_bf16(acc[i][j], al[i], bh);
                }
            }
        }
        __syncthreads();
    }

    // ---- epilogue ----
#pragma unroll
    for (int i = 0; i < 2; i++) {
        int row0 = m0 + warp_m * 32 + i * 16 + lq;
        int row1 = row0 + 8;
        float bv0 = 0.f, bv1 = 0.f;
        if (bias) {
            if (row0 < M) bv0 = bias[row0];
            if (row1 < M) bv1 = bias[row1];
        }
#pragma unroll
        for (int j = 0; j < 8; j++) {
            int col = n0 + warp_n * 64 + j * 8 + lr * 2;
            float2 o0, o1;
            o0.x = acc[i][j][0] + bv0; o0.y = acc[i][j][1] + bv0;
            o1.x = acc[i][j][2] + bv1; o1.y = acc[i][j][3] + bv1;
            if (relu) {
                o0.x = fmaxf(o0.x, 0.f); o0.y = fmaxf(o0.y, 0.f);
                o1.x = fmaxf(o1.x, 0.f); o1.y = fmaxf(o1.y, 0.f);
            }
            if (row0 < M)
                *(float2*)&out[((size_t)b * M + row0) * N + col] = o0;
            if (row1 < M)
                *(float2*)&out[((size_t)b * M + row1) * N + col] = o1;
        }
    }
}

// ------------------------- elementwise kernels -----------------------------
__global__ __launch_bounds__(256)
void upsample2x_kernel(const float* __restrict__ src0,
                       const float* __restrict__ src1,
                       int Csplit, int C, int Hin, int Win,
                       float* __restrict__ dst)
{
    const int Hout = Hin * 2, Wout = Win * 2;
    const long total = (long)NB * C * Hout * Wout;
    long idx = (long)blockIdx.x * blockDim.x + threadIdx.x;
    if (idx >= total) return;
    int x = (int)(idx % Wout);
    int y = (int)((idx / Wout) % Hout);
    int c = (int)((idx / ((long)Wout * Hout)) % C);
    int b = (int)(idx / ((long)Wout * Hout * C));
    float sy = y * 0.5f - 0.25f, sx = x * 0.5f - 0.25f;
    float y0f = floorf(sy), x0f = floorf(sx);
    float fy = sy - y0f, fx = sx - x0f;
    int y0 = (int)y0f, x0 = (int)x0f;
    int y0c = min(max(y0, 0), Hin - 1), y1c = min(max(y0 + 1, 0), Hin - 1);
    int x0c = min(max(x0, 0), Win - 1), x1c = min(max(x0 + 1, 0), Win - 1);
    const float* s = (c < Csplit)
        ? src0 + (size_t)(b * Csplit + c) * Hin * Win
        : src1 + (size_t)(b * (C - Csplit) + (c - Csplit)) * Hin * Win;
    float v00 = s[y0c * Win + x0c], v01 = s[y0c * Win + x1c];
    float v10 = s[y1c * Win + x0c], v11 = s[y1c * Win + x1c];
    dst[idx] = (1.f - fy) * ((1.f - fx) * v00 + fx * v01)
             +         fy * ((1.f - fx) * v10 + fx * v11);
}

__global__ __launch_bounds__(256)
void dcn_sample_kernel(const float* __restrict__ x, const float* __restrict__ om,
                       float* __restrict__ col, int H, int W)
{
    const int HW = H * W;
    const int total = NB * 72 * HW;
    int idx = blockIdx.x * blockDim.x + threadIdx.x;
    if (idx >= total) return;
    int p = idx % HW, gk = (idx / HW) % 72, b = idx / (72 * HW);
    int g = gk / 9, k = gk - g * 9;
    int h = p / W, w = p - h * W;
    float offy = om[((size_t)b * 216 +       gk) * HW + p];
    float offx = om[((size_t)b * 216 + 72 +  gk) * HW + p];
    float mraw = om[((size_t)b * 216 + 144 + gk) * HW + p];
    float msk = 1.f / (1.f + expf(-mraw));
    float yy = (float)h + (float)(k / 3 - 1) + offy;
    float xx = (float)w + (float)(k % 3 - 1) + offx;
    yy = fminf(fmaxf(yy, -1.0e6f), 1.0e6f);
    xx = fminf(fmaxf(xx, -1.0e6f), 1.0e6f);
    float y0f = floorf(yy), x0f = floorf(xx);
    int y0 = (int)y0f, x0 = (int)x0f;
    float fy = yy - y0f, fx = xx - x0f;
    bool vy0 = (y0 >= 0) && (y0 < H), vy1 = (y0 + 1 >= 0) && (y0 + 1 < H);
    bool vx0 = (x0 >= 0) && (x0 < W), vx1 = (x0 + 1 >= 0) && (x0 + 1 < W);
    int cy0 = min(max(y0, 0), H - 1), cy1 = min(max(y0 + 1, 0), H - 1);
    int cx0 = min(max(x0, 0), W - 1), cx1 = min(max(x0 + 1, 0), W - 1);
    float w00 = (vy0 && vx0) ? (1.f - fy) * (1.f - fx) * msk : 0.f;
    float w01 = (vy0 && vx1) ? (1.f - fy) * fx * msk : 0.f;
    float w10 = (vy1 && vx0) ? fy * (1.f - fx) * msk : 0.f;
    float w11 = (vy1 && vx1) ? fy * fx * msk : 0.f;
    int i00 = cy0 * W + cx0, i01 = cy0 * W + cx1;
    int i10 = cy1 * W + cx0, i11 = cy1 * W + cx1;
    const float* xb = x + (size_t)(b * 256 + g * 32) * HW;
    float* cb = col + ((size_t)b * 2304 + (size_t)(g * 32) * 9 + k) * HW + p;
#pragma unroll 4
    for (int c = 0; c < 32; c++) {
        const float* xc = xb + (size_t)c * HW;
        float v = w00 * xc[i00] + w01 * xc[i01] + w10 * xc[i10] + w11 * xc[i11];
        cb[(size_t)c * 9 * HW] = v;
    }
}

__global__ __launch_bounds__(256)
void meanmax_kernel(const float* __restrict__ f2, float* __restrict__ mm)
{
    int p = blockIdx.x * blockDim.x + threadIdx.x;
    int b = blockIdx.y;
    if (p >= 16384) return;
    const float* base = f2 + (size_t)b * 512 * 16384 + p;
    float s = 0.f, mx = -3.402823466e38f;
    for (int c = 0; c < 512; c++) {
        float v = base[(size_t)c * 16384];
        s += v;
        mx = fmaxf(mx, v);
    }
    mm[((size_t)b * 2 + 0) * 16384 + p] = s * (1.f / 512.f);
    mm[((size_t)b * 2 + 1) * 16384 + p] = mx;
}

__global__ __launch_bounds__(256)
void sa_kernel(const float* __restrict__ mm, const float* __restrict__ wsa,
               const float* __restrict__ bng, const float* __restrict__ bnb,
               const float* __restrict__ bnm, const float* __restrict__ bnv,
               float* __restrict__ sa)
{
    int p = blockIdx.x * blockDim.x + threadIdx.x;
    int b = blockIdx.y;
    if (p >= 16384) return;
    int y = p >> 7, x = p & 127;
    float acc = 0.f;
#pragma unroll
    for (int ic = 0; ic < 2; ic++) {
        const float* src = mm + ((size_t)b * 2 + ic) * 16384;
        const float* wk = wsa + ic * 49;
#pragma unroll
        for (int ky = 0; ky < 7; ky++) {
            int yy = y + ky - 3;
            if ((unsigned)yy >= 128u) continue;
#pragma unroll
            for (int kx = 0; kx < 7; kx++) {
                int xx = x + kx - 3;
                if ((unsigned)xx >= 128u) continue;
                acc += src[yy * 128 + xx] * wk[ky * 7 + kx];
            }
        }
    }
    float a = (acc - bnm[0]) * rsqrtf(bnv[0] + 1e-5f) * bng[0] + bnb[0];
    sa[(size_t)b * 16384 + p] = 1.f / (1.f + expf(-a));
}

__global__ __launch_bounds__(256)
void gn_reduce_kernel(const float* __restrict__ y, float* __restrict__ stats)
{
    const int bg = blockIdx.x;
    const float* base = y + (size_t)bg * 8 * 16384;
    float s = 0.f, sq = 0.f;
    for (int i = threadIdx.x; i < 8 * 16384; i += 256) {
        float v = base[i];
        s += v;
        sq += v * v;
    }
    __shared__ float ss[256], ssq[256];
    ss[threadIdx.x] = s;
    ssq[threadIdx.x] = sq;
    __syncthreads();
    for (int st = 128; st > 0; st >>= 1) {
        if (threadIdx.x < st) {
            ss[threadIdx.x] += ss[threadIdx.x + st];
            ssq[threadIdx.x] += ssq[threadIdx.x + st];
        }
        __syncthreads();
    }
    if (threadIdx.x == 0) {
        const float inv = 1.f / (8.f * 16384.f);
        float mean = ss[0] * inv;
        float var = ssq[0] * inv - mean * mean;
        stats[bg * 2 + 0] = mean;
        stats[bg * 2 + 1] = rsqrtf(var + 1e-5f);
    }
}

__global__ __launch_bounds__(256)
void gn_apply_kernel(const float* __restrict__ y, const float* __restrict__ stats,
                     const float* __restrict__ gg, const float* __restrict__ gb,
                     float* __restrict__ out)
{
    size_t idx = (size_t)blockIdx.x * blockDim.x + threadIdx.x;
    if (idx >= (size_t)16777216) return;
    int c = (int)((idx >> 14) & 255);
    int b = (int)(idx >> 22);
    int g = c >> 3;
    float mean = stats[(b * 32 + g) * 2 + 0];
    float rstd = stats[(b * 32 + g) * 2 + 1];
    out[idx] = (y[idx] - mean) * rstd * gg[c] + gb[c];
}

// ------------------------------ host ---------------------------------------
static void* symaddr(const void* sym)
{
    void* p = nullptr;
    cudaGetSymbolAddress(&p, sym);
    return p;
}

extern "C" void kernel_launch(void* const* d_in, const int* in_sizes, int n_in,
                              void* d_out, int out_size)
{
    (void)in_sizes; (void)n_in; (void)out_size;
    const float* feat_3 = (const float*)d_in[1];
    const float* feat_4 = (const float*)d_in[2];
    const float* feat_5 = (const float*)d_in[3];
    const float* w_off5 = (const float*)d_in[4];
    const float* w_om5  = (const float*)d_in[5];
    const float* b_om5  = (const float*)d_in[6];
    const float* w_dcn5 = (const float*)d_in[7];
    const float* b_dcn5 = (const float*)d_in[8];
    const float* w_c1   = (const float*)d_in[9];
    const float* w_off4 = (const float*)d_in[10];
    const float* w_om4  = (const float*)d_in[11];
    const float* b_om4  = (const float*)d_in[12];
    const float* w_dcn4 = (const float*)d_in[13];
    const float* b_dcn4 = (const float*)d_in[14];
    const float* w_sa   = (const float*)d_in[15];
    const float* bn_g   = (const float*)d_in[16];
    const float* bn_b   = (const float*)d_in[17];
    const float* bn_m   = (const float*)d_in[18];
    const float* bn_v   = (const float*)d_in[19];
    const float* w_sem  = (const float*)d_in[20];
    const float* gn_g   = (const float*)d_in[21];
    const float* gn_b   = (const float*)d_in[22];
    float* out = (float*)d_out;

    float* up5  = (float*)symaddr(g_up5);
    float* off5 = (float*)symaddr(g_off5);
    float* om5  = (float*)symaddr(g_om5);
    float* col  = (float*)symaddr(g_col);
    float* al5  = (float*)symaddr(g_al5);
    float* c1b  = (float*)symaddr(g_c1b);
    float* up4  = (float*)symaddr(g_up4);
    float* off4 = (float*)symaddr(g_off4);
    float* om4  = (float*)symaddr(g_om4);
    float* al4  = (float*)symaddr(g_al4);
    float* f2   = (float*)symaddr(g_f2);
    float* mm   = (float*)symaddr(g_mm);
    float* sab  = (float*)symaddr(g_sab);
    float* ybuf = (float*)symaddr(g_y);
    float* st   = (float*)symaddr(g_st);
    __nv_bfloat16* wp = (__nv_bfloat16*)symaddr(g_wp);

    cudaFuncSetAttribute(gemm_mma_kernel<0>, cudaFuncAttributeMaxDynamicSharedMemorySize, SMEM_DYN);
    cudaFuncSetAttribute(gemm_mma_kernel<1>, cudaFuncAttributeMaxDynamicSharedMemorySize, SMEM_DYN);
    cudaFuncSetAttribute(gemm_mma_kernel<2>, cudaFuncAttributeMaxDynamicSharedMemorySize, SMEM_DYN);
    cudaFuncSetAttribute(gemm_mma_kernel<3>, cudaFuncAttributeMaxDynamicSharedMemorySize, SMEM_DYN);

    // weight prep (graph-capturable, cheap)
    prep_w_kernel<<<512, 256>>>(w_off5, wp + WP_OFF5, 256, 512);
    prep_w_kernel<<<2304, 256>>>(w_om5,  wp + WP_OM5, 216, 2304);
    prep_w_kernel<<<2304, 256>>>(w_dcn5, wp + WP_DCN5, 256, 2304);
    prep_w_kernel<<<512, 256>>>(w_c1,   wp + WP_C1, 256, 512);
    prep_w_kernel<<<512, 256>>>(w_off4, wp + WP_OFF4, 256, 512);
    prep_w_kernel<<<2304, 256>>>(w_om4,  wp + WP_OM4, 216, 2304);
    prep_w_kernel<<<2304, 256>>>(w_dcn4, wp + WP_DCN4, 256, 2304);
    prep_w_kernel<<<512, 256>>>(w_sem,  wp + WP_SEM, 256, 512);

    // ----- level 5 (16 -> 32), N=1024 -----
    upsample2x_kernel<<<(4 * 256 * 1024 + 255) / 256, 256>>>(
        feat_5, feat_5, 256, 256, 16, 16, up5);
    gemm_mma_kernel<1><<<dim3(8, 2, NB), 256, SMEM_DYN>>>(
        wp + WP_OFF5, feat_4, up5, nullptr, nullptr, off5,
        256, 512, 1024, 256, 2.0f, 0, 0, 0);
    gemm_mma_kernel<2><<<dim3(8, 2, NB), 256, SMEM_DYN>>>(
        wp + WP_OM5, off5, nullptr, b_om5, nullptr, om5,
        216, 2304, 1024, 0, 0.f, 32, 32, 0);
    dcn_sample_kernel<<<(NB * 72 * 1024 + 255) / 256, 256>>>(up5, om5, col, 32, 32);
    gemm_mma_kernel<0><<<dim3(8, 2, NB), 256, SMEM_DYN>>>(
        wp + WP_DCN5, col, nullptr, b_dcn5, nullptr, al5,
        256, 2304, 1024, 0, 0.f, 0, 0, 1);
    gemm_mma_kernel<1><<<dim3(8, 2, NB), 256, SMEM_DYN>>>(
        wp + WP_C1, al5, feat_4, nullptr, nullptr, c1b,
        256, 512, 1024, 256, 1.0f, 0, 0, 0);

    // ----- level 4 (32 -> 64), N=4096 -----
    upsample2x_kernel<<<(4 * 256 * 4096 + 255) / 256, 256>>>(
        c1b, c1b, 256, 256, 32, 32, up4);
    gemm_mma_kernel<1><<<dim3(32, 2, NB), 256, SMEM_DYN>>>(
        wp + WP_OFF4, feat_3, up4, nullptr, nullptr, off4,
        256, 512, 4096, 256, 2.0f, 0, 0, 0);
    gemm_mma_kernel<2><<<dim3(32, 2, NB), 256, SMEM_DYN>>>(
        wp + WP_OM4, off4, nullptr, b_om4, nullptr, om4,
        216, 2304, 4096, 0, 0.f, 64, 64, 0);
    dcn_sample_kernel<<<(NB * 72 * 4096 + 255) / 256, 256>>>(up4, om4, col, 64, 64);
    gemm_mma_kernel<0><<<dim3(32, 2, NB), 256, SMEM_DYN>>>(
        wp + WP_DCN4, col, nullptr, b_dcn4, nullptr, al4,
        256, 2304, 4096, 0, 0.f, 0, 0, 1);

    // ----- feat_2 + SEM -----
    upsample2x_kernel<<<(unsigned)((4L * 512 * 16384 + 255) / 256), 256>>>(
        al4, feat_3, 256, 512, 64, 64, f2);
    meanmax_kernel<<<dim3(64, NB), 256>>>(f2, mm);
    sa_kernel<<<dim3(64, NB), 256>>>(mm, w_sa, bn_g, bn_b, bn_m, bn_v, sab);
    gemm_mma_kernel<3><<<dim3(128, 2, NB), 256, SMEM_DYN>>>(
        wp + WP_SEM, f2, nullptr, nullptr, sab, ybuf,
        256, 512, 16384, 0, 0.f, 0, 0, 0);
    gn_reduce_kernel<<<128, 256>>>(ybuf, st);
    gn_apply_kernel<<<65536, 256>>>(ybuf, st, gn_g, gn_b, out);
}

// round 12
// speedup vs baseline: 1.6822x; 1.4611x over previous
#include <cuda_runtime.h>
#include <cuda_bf16.h>
#include <cstdint>

#define NB 4

// ------------------------- static scratch buffers --------------------------
static __device__ float g_up5 [4u * 256u * 32u * 32u];
static __device__ float g_off5[4u * 256u * 32u * 32u];
static __device__ float g_om5 [4u * 216u * 32u * 32u];
static __device__ float g_col [4u * 2304u * 64u * 64u];
static __device__ float g_al5 [4u * 256u * 32u * 32u];
static __device__ float g_c1b [4u * 256u * 32u * 32u];
static __device__ float g_up4 [4u * 256u * 64u * 64u];
static __device__ float g_off4[4u * 256u * 64u * 64u];
static __device__ float g_om4 [4u * 216u * 64u * 64u];
static __device__ float g_al4 [4u * 256u * 64u * 64u];
static __device__ float g_f2  [4u * 512u * 128u * 128u];
static __device__ float g_mm  [4u * 2u * 128u * 128u];
static __device__ float g_sab [4u * 128u * 128u];
static __device__ float g_y   [4u * 256u * 128u * 128u];
static __device__ float g_st  [256];
// pre-split weights: [hi(256*K) | lo(256*K)] bf16, M zero-padded to 256
static __device__ __align__(16) __nv_bfloat16 g_wp[5767168];
#define WP_OFF5 0u
#define WP_OM5  262144u
#define WP_DCN5 1441792u
#define WP_C1   2621440u
#define WP_OFF4 2883584u
#define WP_OM4  3145728u
#define WP_DCN4 4325376u
#define WP_SEM  5505024u

__device__ __forceinline__ uint32_t smem_to_u32(const void* p) {
    uint32_t a;
    asm("{ .reg .u64 t; cvta.to.shared.u64 t, %1; cvt.u32.u64 %0, t; }"
        : "=r"(a) : "l"(p));
    return a;
}

// ---------------------------------------------------------------------------
// Weight prep: W[M][K] fp32 -> out[0..256*K) = hi bf16, out[256*K..) = lo bf16
// ---------------------------------------------------------------------------
__global__ __launch_bounds__(256)
void prep_w_kernel(const float* __restrict__ W, __nv_bfloat16* __restrict__ out,
                   int M, int K)
{
    int idx = blockIdx.x * 256 + threadIdx.x;
    if (idx >= 256 * K) return;
    int m = idx / K, k = idx - m * K;
    float v = (m < M) ? W[(size_t)m * K + k] : 0.f;
    __nv_bfloat16 hi = __float2bfloat16(v);
    __nv_bfloat16 lo = __float2bfloat16(v - __bfloat162float(hi));
    out[idx] = hi;
    out[(size_t)256 * K + idx] = lo;
}

// X loader modes: 0 plain [K][N], 1 concat(+scale), 2 im2col3x3 pad1, 3 (1+sa)
template<int MODE>
__device__ __forceinline__ float loadX(const float* __restrict__ X0,
                                       const float* __restrict__ X1,
                                       const float* __restrict__ sa,
                                       int b, int k, int p,
                                       int K, int N, int Csplit, float scale1,
                                       int Hin, int Win)
{
    if (MODE == 0) return X0[((size_t)b * K + k) * N + p];
    else if (MODE == 1) {
        if (k < Csplit) return X0[((size_t)b * Csplit + k) * N + p];
        return scale1 * X1[((size_t)b * (K - Csplit) + (k - Csplit)) * N + p];
    } else if (MODE == 2) {
        int cin = k / 9, t = k - cin * 9;
        int hh = p / Win + (t / 3) - 1;
        int ww = (p - (p / Win) * Win) + (t - (t / 3) * 3) - 1;
        if ((unsigned)hh < (unsigned)Hin && (unsigned)ww < (unsigned)Win)
            return X0[(((size_t)b * (K / 9) + cin) * Hin + hh) * Win + ww];
        return 0.f;
    } else return X0[((size_t)b * K + k) * N + p] * (1.f + sa[(size_t)b * N + p]);
}

__device__ __forceinline__ void mma_bf16(float* c, const unsigned* a, const unsigned* b)
{
    asm volatile(
        "mma.sync.aligned.m16n8k16.row.col.f32.bf16.bf16.f32 "
        "{%0,%1,%2,%3}, {%4,%5,%6,%7}, {%8,%9}, {%0,%1,%2,%3};"
        : "+f"(c[0]), "+f"(c[1]), "+f"(c[2]), "+f"(c[3])
        : "r"(a[0]), "r"(a[1]), "r"(a[2]), "r"(a[3]), "r"(b[0]), "r"(b[1]));
}
#define LDSM_X4(R, addr) \
    asm volatile("ldmatrix.sync.aligned.m8n8.x4.shared.b16 {%0,%1,%2,%3}, [%4];" \
        : "=r"((R)[0]), "=r"((R)[1]), "=r"((R)[2]), "=r"((R)[3]) : "r"(addr))

__device__ __forceinline__ unsigned bf2(__nv_bfloat16 a, __nv_bfloat16 b)
{
    return (unsigned)__bfloat16_as_ushort(a) | ((unsigned)__bfloat16_as_ushort(b) << 16);
}

// ---------------------------------------------------------------------------
// mma.sync bf16 split GEMM, pipelined:
//  - A tiles (pre-split weights) via cp.async, double-buffered in smem
//  - X tile prefetched to regs during compute, converted+stored after sync
//  - fragments via ldmatrix.x4 (conflict-free odd-16B-unit strides)
// Block 128(M) x 128(N), BK=32, 256 thr (8 warps = 4M x 2N), warp tile 32x64.
// acc += Ah*Xh + Ah*Xl + Al*Xh  (fp32 accum; error-free to ~2^-16).
// SMEM: A0[36864] A1[36864] Xh[10240] Xl[10240] = 94208 B, 2 CTAs/SM.
// ---------------------------------------------------------------------------
#define SMEM_DYN 94208

template<int MODE>
__global__ __launch_bounds__(256, 2)
void gemm_mma_kernel(const __nv_bfloat16* __restrict__ Wp,
                     const float* __restrict__ X0, const float* __restrict__ X1,
                     const float* __restrict__ bias, const float* __restrict__ sa,
                     float* __restrict__ out,
                     int M, int K, int N, int Csplit, float scale1,
                     int Hin, int Win, int relu)
{
    extern __shared__ char smem[];
    const uint32_t su = smem_to_u32(smem);
    unsigned* Xh32 = (unsigned*)(smem + 73728);
    unsigned* Xl32 = (unsigned*)(smem + 83968);

    const int tid = threadIdx.x;
    const int wid = tid >> 5, lane = tid & 31;
    const int warp_m = wid & 3;
    const int warp_n = wid >> 2;
    const int lq = lane >> 2;
    const int lr = lane & 3;
    const int m0 = blockIdx.y * 128;
    const int n0 = blockIdx.x * 128;
    const int b  = blockIdx.z;
    const int NC = K / 32;
    const size_t loStride = (size_t)256 * K;

    float acc[2][8][4];
#pragma unroll
    for (int i = 0; i < 2; i++)
#pragma unroll
        for (int j = 0; j < 8; j++)
#pragma unroll
            for (int q = 0; q < 4; q++) acc[i][j][q] = 0.f;

    // per-lane ldmatrix row offsets (bytes, relative to tile bases)
    const int ar = lane & 7, aj = lane >> 3;
    uint32_t aoff[2];
#pragma unroll
    for (int i = 0; i < 2; i++)
        aoff[i] = (uint32_t)((warp_m * 32 + i * 16 + ar + (aj & 1) * 8) * 144
                             + (aj >> 1) * 16);
    uint32_t boff[4];
#pragma unroll
    for (int jp = 0; jp < 4; jp++)
        boff[jp] = 73728u + (uint32_t)((warp_n * 64 + jp * 16 + (aj >> 1) * 8 + ar) * 80
                                       + (aj & 1) * 16);

    auto prefA = [&](int c, int buf) {
        uint32_t sb = su + (uint32_t)buf * 36864u;
#pragma unroll
        for (int r = 0; r < 4; r++) {
            int idx = tid + r * 256;
            int plane = idx >> 9;
            int rem = idx & 511;
            int m = rem & 127, q = rem >> 7;
            const __nv_bfloat16* g = Wp + (size_t)plane * loStride
                                   + (size_t)(m0 + m) * K + c * 32 + q * 8;
            uint32_t d = sb + (uint32_t)plane * 18432u + (uint32_t)(m * 144 + q * 16);
            asm volatile("cp.async.cg.shared.global [%0], [%1], 16;" :: "r"(d), "l"(g));
        }
        asm volatile("cp.async.commit_group;");
    };

    const int xn = tid & 127, xkh = tid >> 7;
    auto prefX = [&](int c, float* xv) {
#pragma unroll
        for (int rr = 0; rr < 8; rr++) {
            int k = c * 32 + xkh * 16 + rr * 2;
            xv[rr * 2]     = loadX<MODE>(X0, X1, sa, b, k,     n0 + xn, K, N, Csplit, scale1, Hin, Win);
            xv[rr * 2 + 1] = loadX<MODE>(X0, X1, sa, b, k + 1, n0 + xn, K, N, Csplit, scale1, Hin, Win);
        }
    };
    auto storeX = [&](const float* xv) {
#pragma unroll
        for (int rr = 0; rr < 8; rr++) {
            float v0 = xv[rr * 2], v1 = xv[rr * 2 + 1];
            __nv_bfloat16 h0 = __float2bfloat16(v0), h1 = __float2bfloat16(v1);
            __nv_bfloat16 l0 = __float2bfloat16(v0 - __bfloat162float(h0));
            __nv_bfloat16 l1 = __float2bfloat16(v1 - __bfloat162float(h1));
            Xh32[xn * 20 + xkh * 8 + rr] = bf2(h0, h1);
            Xl32[xn * 20 + xkh * 8 + rr] = bf2(l0, l1);
        }
    };

    auto compute = [&](int buf) {
        uint32_t aBase = su + (uint32_t)buf * 36864u;
#pragma unroll
        for (int ks = 0; ks < 2; ks++) {
            unsigned ah[2][4], al[2][4];
#pragma unroll
            for (int i = 0; i < 2; i++) {
                LDSM_X4(ah[i], aBase + aoff[i] + ks * 32);
                LDSM_X4(al[i], aBase + 18432u + aoff[i] + ks * 32);
            }
#pragma unroll
            for (int jp = 0; jp < 4; jp++) {
                unsigned bh[4], bl[4];
                LDSM_X4(bh, su + boff[jp] + ks * 32);
                LDSM_X4(bl, su + boff[jp] + 10240u + ks * 32);
#pragma unroll
                for (int jo = 0; jo < 2; jo++) {
                    int j = jp * 2 + jo;
#pragma unroll
                    for (int i = 0; i < 2; i++) {
                        mma_bf16(acc[i][j], ah[i], bh + jo * 2);
                        mma_bf16(acc[i][j], ah[i], bl + jo * 2);
                        mma_bf16(acc[i][j], al[i], bh + jo * 2);
                    }
                }
            }
        }
    };

    float xv[16];
    prefA(0, 0);
    prefX(0, xv);
    storeX(xv);
    asm volatile("cp.async.wait_group 0;");
    __syncthreads();

    for (int c = 0; c < NC; c++) {
        int cur = c & 1;
        bool more = (c + 1 < NC);
        if (more) {
            prefA(c + 1, cur ^ 1);
            prefX(c + 1, xv);
        }
        compute(cur);
        __syncthreads();
        if (more) {
            storeX(xv);
            asm volatile("cp.async.wait_group 0;");
            __syncthreads();
        }
    }

    // ---- epilogue ----
#pragma unroll
    for (int i = 0; i < 2; i++) {
        int row0 = m0 + warp_m * 32 + i * 16 + lq;
        int row1 = row0 + 8;
        float bv0 = 0.f, bv1 = 0.f;
        if (bias) {
            if (row0 < M) bv0 = bias[row0];
            if (row1 < M) bv1 = bias[row1];
        }
#pragma unroll
        for (int j = 0; j < 8; j++) {
            int col = n0 + warp_n * 64 + j * 8 + lr * 2;
            float2 o0, o1;
            o0.x = acc[i][j][0] + bv0; o0.y = acc[i][j][1] + bv0;
            o1.x = acc[i][j][2] + bv1; o1.y = acc[i][j][3] + bv1;
            if (relu) {
                o0.x = fmaxf(o0.x, 0.f); o0.y = fmaxf(o0.y, 0.f);
                o1.x = fmaxf(o1.x, 0.f); o1.y = fmaxf(o1.y, 0.f);
            }
            if (row0 < M)
                *(float2*)&out[((size_t)b * M + row0) * N + col] = o0;
            if (row1 < M)
                *(float2*)&out[((size_t)b * M + row1) * N + col] = o1;
        }
    }
}

// ------------------------- elementwise kernels -----------------------------
__global__ __launch_bounds__(256)
void upsample2x_kernel(const float* __restrict__ src0,
                       const float* __restrict__ src1,
                       int Csplit, int C, int Hin, int Win,
                       float* __restrict__ dst)
{
    const int Hout = Hin * 2, Wout = Win * 2;
    const long total = (long)NB * C * Hout * Wout;
    long idx = (long)blockIdx.x * blockDim.x + threadIdx.x;
    if (idx >= total) return;
    int x = (int)(idx % Wout);
    int y = (int)((idx / Wout) % Hout);
    int c = (int)((idx / ((long)Wout * Hout)) % C);
    int b = (int)(idx / ((long)Wout * Hout * C));
    float sy = y * 0.5f - 0.25f, sx = x * 0.5f - 0.25f;
    float y0f = floorf(sy), x0f = floorf(sx);
    float fy = sy - y0f, fx = sx - x0f;
    int y0 = (int)y0f, x0 = (int)x0f;
    int y0c = min(max(y0, 0), Hin - 1), y1c = min(max(y0 + 1, 0), Hin - 1);
    int x0c = min(max(x0, 0), Win - 1), x1c = min(max(x0 + 1, 0), Win - 1);
    const float* s = (c < Csplit)
        ? src0 + (size_t)(b * Csplit + c) * Hin * Win
        : src1 + (size_t)(b * (C - Csplit) + (c - Csplit)) * Hin * Win;
    float v00 = s[y0c * Win + x0c], v01 = s[y0c * Win + x1c];
    float v10 = s[y1c * Win + x0c], v11 = s[y1c * Win + x1c];
    dst[idx] = (1.f - fy) * ((1.f - fx) * v00 + fx * v01)
             +         fy * ((1.f - fx) * v10 + fx * v11);
}

__global__ __launch_bounds__(256)
void dcn_sample_kernel(const float* __restrict__ x, const float* __restrict__ om,
                       float* __restrict__ col, int H, int W)
{
    const int HW = H * W;
    const int total = NB * 72 * HW;
    int idx = blockIdx.x * blockDim.x + threadIdx.x;
    if (idx >= total) return;
    int p = idx % HW, gk = (idx / HW) % 72, b = idx / (72 * HW);
    int g = gk / 9, k = gk - g * 9;
    int h = p / W, w = p - h * W;
    float offy = om[((size_t)b * 216 +       gk) * HW + p];
    float offx = om[((size_t)b * 216 + 72 +  gk) * HW + p];
    float mraw = om[((size_t)b * 216 + 144 + gk) * HW + p];
    float msk = 1.f / (1.f + expf(-mraw));
    float yy = (float)h + (float)(k / 3 - 1) + offy;
    float xx = (float)w + (float)(k % 3 - 1) + offx;
    yy = fminf(fmaxf(yy, -1.0e6f), 1.0e6f);
    xx = fminf(fmaxf(xx, -1.0e6f), 1.0e6f);
    float y0f = floorf(yy), x0f = floorf(xx);
    int y0 = (int)y0f, x0 = (int)x0f;
    float fy = yy - y0f, fx = xx - x0f;
    bool vy0 = (y0 >= 0) && (y0 < H), vy1 = (y0 + 1 >= 0) && (y0 + 1 < H);
    bool vx0 = (x0 >= 0) && (x0 < W), vx1 = (x0 + 1 >= 0) && (x0 + 1 < W);
    int cy0 = min(max(y0, 0), H - 1), cy1 = min(max(y0 + 1, 0), H - 1);
    int cx0 = min(max(x0, 0), W - 1), cx1 = min(max(x0 + 1, 0), W - 1);
    float w00 = (vy0 && vx0) ? (1.f - fy) * (1.f - fx) * msk : 0.f;
    float w01 = (vy0 && vx1) ? (1.f - fy) * fx * msk : 0.f;
    float w10 = (vy1 && vx0) ? fy * (1.f - fx) * msk : 0.f;
    float w11 = (vy1 && vx1) ? fy * fx * msk : 0.f;
    int i00 = cy0 * W + cx0, i01 = cy0 * W + cx1;
    int i10 = cy1 * W + cx0, i11 = cy1 * W + cx1;
    const float* xb = x + (size_t)(b * 256 + g * 32) * HW;
    float* cb = col + ((size_t)b * 2304 + (size_t)(g * 32) * 9 + k) * HW + p;
#pragma unroll 4
    for (int c = 0; c < 32; c++) {
        const float* xc = xb + (size_t)c * HW;
        float v = w00 * xc[i00] + w01 * xc[i01] + w10 * xc[i10] + w11 * xc[i11];
        cb[(size_t)c * 9 * HW] = v;
    }
}

__global__ __launch_bounds__(256)
void meanmax_kernel(const float* __restrict__ f2, float* __restrict__ mm)
{
    int p = blockIdx.x * blockDim.x + threadIdx.x;
    int b = blockIdx.y;
    if (p >= 16384) return;
    const float* base = f2 + (size_t)b * 512 * 16384 + p;
    float s = 0.f, mx = -3.402823466e38f;
    for (int c = 0; c < 512; c++) {
        float v = base[(size_t)c * 16384];
        s += v;
        mx = fmaxf(mx, v);
    }
    mm[((size_t)b * 2 + 0) * 16384 + p] = s * (1.f / 512.f);
    mm[((size_t)b * 2 + 1) * 16384 + p] = mx;
}

__global__ __launch_bounds__(256)
void sa_kernel(const float* __restrict__ mm, const float* __restrict__ wsa,
               const float* __restrict__ bng, const float* __restrict__ bnb,
               const float* __restrict__ bnm, const float* __restrict__ bnv,
               float* __restrict__ sa)
{
    int p = blockIdx.x * blockDim.x + threadIdx.x;
    int b = blockIdx.y;
    if (p >= 16384) return;
    int y = p >> 7, x = p & 127;
    float acc = 0.f;
#pragma unroll
    for (int ic = 0; ic < 2; ic++) {
        const float* src = mm + ((size_t)b * 2 + ic) * 16384;
        const float* wk = wsa + ic * 49;
#pragma unroll
        for (int ky = 0; ky < 7; ky++) {
            int yy = y + ky - 3;
            if ((unsigned)yy >= 128u) continue;
#pragma unroll
            for (int kx = 0; kx < 7; kx++) {
                int xx = x + kx - 3;
                if ((unsigned)xx >= 128u) continue;
                acc += src[yy * 128 + xx] * wk[ky * 7 + kx];
            }
        }
    }
    float a = (acc - bnm[0]) * rsqrtf(bnv[0] + 1e-5f) * bng[0] + bnb[0];
    sa[(size_t)b * 16384 + p] = 1.f / (1.f + expf(-a));
}

__global__ __launch_bounds__(256)
void gn_reduce_kernel(const float* __restrict__ y, float* __restrict__ stats)
{
    const int bg = blockIdx.x;
    const float* base = y + (size_t)bg * 8 * 16384;
    float s = 0.f, sq = 0.f;
    for (int i = threadIdx.x; i < 8 * 16384; i += 256) {
        float v = base[i];
        s += v;
        sq += v * v;
    }
    __shared__ float ss[256], ssq[256];
    ss[threadIdx.x] = s;
    ssq[threadIdx.x] = sq;
    __syncthreads();
    for (int st = 128; st > 0; st >>= 1) {
        if (threadIdx.x < st) {
            ss[threadIdx.x] += ss[threadIdx.x + st];
            ssq[threadIdx.x] += ssq[threadIdx.x + st];
        }
        __syncthreads();
    }
    if (threadIdx.x == 0) {
        const float inv = 1.f / (8.f * 16384.f);
        float mean = ss[0] * inv;
        float var = ssq[0] * inv - mean * mean;
        stats[bg * 2 + 0] = mean;
        stats[bg * 2 + 1] = rsqrtf(var + 1e-5f);
    }
}

__global__ __launch_bounds__(256)
void gn_apply_kernel(const float* __restrict__ y, const float* __restrict__ stats,
                     const float* __restrict__ gg, const float* __restrict__ gb,
                     float* __restrict__ out)
{
    size_t idx = (size_t)blockIdx.x * blockDim.x + threadIdx.x;
    if (idx >= (size_t)16777216) return;
    int c = (int)((idx >> 14) & 255);
    int b = (int)(idx >> 22);
    int g = c >> 3;
    float mean = stats[(b * 32 + g) * 2 + 0];
    float rstd = stats[(b * 32 + g) * 2 + 1];
    out[idx] = (y[idx] - mean) * rstd * gg[c] + gb[c];
}

// ------------------------------ host ---------------------------------------
static void* symaddr(const void* sym)
{
    void* p = nullptr;
    cudaGetSymbolAddress(&p, sym);
    return p;
}

extern "C" void kernel_launch(void* const* d_in, const int* in_sizes, int n_in,
                              void* d_out, int out_size)
{
    (void)in_sizes; (void)n_in; (void)out_size;
    const float* feat_3 = (const float*)d_in[1];
    const float* feat_4 = (const float*)d_in[2];
    const float* feat_5 = (const float*)d_in[3];
    const float* w_off5 = (const float*)d_in[4];
    const float* w_om5  = (const float*)d_in[5];
    const float* b_om5  = (const float*)d_in[6];
    const float* w_dcn5 = (const float*)d_in[7];
    const float* b_dcn5 = (const float*)d_in[8];
    const float* w_c1   = (const float*)d_in[9];
    const float* w_off4 = (const float*)d_in[10];
    const float* w_om4  = (const float*)d_in[11];
    const float* b_om4  = (const float*)d_in[12];
    const float* w_dcn4 = (const float*)d_in[13];
    const float* b_dcn4 = (const float*)d_in[14];
    const float* w_sa   = (const float*)d_in[15];
    const float* bn_g   = (const float*)d_in[16];
    const float* bn_b   = (const float*)d_in[17];
    const float* bn_m   = (const float*)d_in[18];
    const float* bn_v   = (const float*)d_in[19];
    const float* w_sem  = (const float*)d_in[20];
    const float* gn_g   = (const float*)d_in[21];
    const float* gn_b   = (const float*)d_in[22];
    float* out = (float*)d_out;

    float* up5  = (float*)symaddr(g_up5);
    float* off5 = (float*)symaddr(g_off5);
    float* om5  = (float*)symaddr(g_om5);
    float* col  = (float*)symaddr(g_col);
    float* al5  = (float*)symaddr(g_al5);
    float* c1b  = (float*)symaddr(g_c1b);
    float* up4  = (float*)symaddr(g_up4);
    float* off4 = (float*)symaddr(g_off4);
    float* om4  = (float*)symaddr(g_om4);
    float* al4  = (float*)symaddr(g_al4);
    float* f2   = (float*)symaddr(g_f2);
    float* mm   = (float*)symaddr(g_mm);
    float* sab  = (float*)symaddr(g_sab);
    float* ybuf = (float*)symaddr(g_y);
    float* st   = (float*)symaddr(g_st);
    __nv_bfloat16* wp = (__nv_bfloat16*)symaddr(g_wp);

    cudaFuncSetAttribute(gemm_mma_kernel<0>, cudaFuncAttributeMaxDynamicSharedMemorySize, SMEM_DYN);
    cudaFuncSetAttribute(gemm_mma_kernel<1>, cudaFuncAttributeMaxDynamicSharedMemorySize, SMEM_DYN);
    cudaFuncSetAttribute(gemm_mma_kernel<2>, cudaFuncAttributeMaxDynamicSharedMemorySize, SMEM_DYN);
    cudaFuncSetAttribute(gemm_mma_kernel<3>, cudaFuncAttributeMaxDynamicSharedMemorySize, SMEM_DYN);

    // ----- level 5 (16 -> 32), launch order puts gemm om5 at launch #6
    // so ncu (-s 5 -c 1) profiles a representative GEMM -----
    prep_w_kernel<<<512, 256>>>(w_off5, wp + WP_OFF5, 256, 512);    // 1
    prep_w_kernel<<<2304, 256>>>(w_om5,  wp + WP_OM5, 216, 2304);   // 2
    prep_w_kernel<<<2304, 256>>>(w_dcn5, wp + WP_DCN5, 256, 2304);  // 3
    upsample2x_kernel<<<(4 * 256 * 1024 + 255) / 256, 256>>>(       // 4
        feat_5, feat_5, 256, 256, 16, 16, up5);
    gemm_mma_kernel<1><<<dim3(8, 2, NB), 256, SMEM_DYN>>>(          // 5
        wp + WP_OFF5, feat_4, up5, nullptr, nullptr, off5,
        256, 512, 1024, 256, 2.0f, 0, 0, 0);
    gemm_mma_kernel<2><<<dim3(8, 2, NB), 256, SMEM_DYN>>>(          // 6 <- profiled
        wp + WP_OM5, off5, nullptr, b_om5, nullptr, om5,
        216, 2304, 1024, 0, 0.f, 32, 32, 0);
    dcn_sample_kernel<<<(NB * 72 * 1024 + 255) / 256, 256>>>(up5, om5, col, 32, 32);
    gemm_mma_kernel<0><<<dim3(8, 2, NB), 256, SMEM_DYN>>>(
        wp + WP_DCN5, col, nullptr, b_dcn5, nullptr, al5,
        256, 2304, 1024, 0, 0.f, 0, 0, 1);
    prep_w_kernel<<<512, 256>>>(w_c1, wp + WP_C1, 256, 512);
    gemm_mma_kernel<1><<<dim3(8, 2, NB), 256, SMEM_DYN>>>(
        wp + WP_C1, al5, feat_4, nullptr, nullptr, c1b,
        256, 512, 1024, 256, 1.0f, 0, 0, 0);

    // ----- level 4 (32 -> 64), N=4096 -----
    prep_w_kernel<<<512, 256>>>(w_off4, wp + WP_OFF4, 256, 512);
    upsample2x_kernel<<<(4 * 256 * 4096 + 255) / 256, 256>>>(
        c1b, c1b, 256, 256, 32, 32, up4);
    gemm_mma_kernel<1><<<dim3(32, 2, NB), 256, SMEM_DYN>>>(
        wp + WP_OFF4, feat_3, up4, nullptr, nullptr, off4,
        256, 512, 4096, 256, 2.0f, 0, 0, 0);
    prep_w_kernel<<<2304, 256>>>(w_om4, wp + WP_OM4, 216, 2304);
    gemm_mma_kernel<2><<<dim3(32, 2, NB), 256, SMEM_DYN>>>(
        wp + WP_OM4, off4, nullptr, b_om4, nullptr, om4,
        216, 2304, 4096, 0, 0.f, 64, 64, 0);
    dcn_sample_kernel<<<(NB * 72 * 4096 + 255) / 256, 256>>>(up4, om4, col, 64, 64);
    prep_w_kernel<<<2304, 256>>>(w_dcn4, wp + WP_DCN4, 256, 2304);
    gemm_mma_kernel<0><<<dim3(32, 2, NB), 256, SMEM_DYN>>>(
        wp + WP_DCN4, col, nullptr, b_dcn4, nullptr, al4,
        256, 2304, 4096, 0, 0.f, 0, 0, 1);

    // ----- feat_2 + SEM -----
    upsample2x_kernel<<<(unsigned)((4L * 512 * 16384 + 255) / 256), 256>>>(
        al4, feat_3, 256, 512, 64, 64, f2);
    prep_w_kernel<<<512, 256>>>(w_sem, wp + WP_SEM, 256, 512);
    meanmax_kernel<<<dim3(64, NB), 256>>>(f2, mm);
    sa_kernel<<<dim3(64, NB), 256>>>(mm, w_sa, bn_g, bn_b, bn_m, bn_v, sab);
    gemm_mma_kernel<3><<<dim3(128, 2, NB), 256, SMEM_DYN>>>(
        wp + WP_SEM, f2, nullptr, nullptr, sab, ybuf,
        256, 512, 16384, 0, 0.f, 0, 0, 0);
    gn_reduce_kernel<<<128, 256>>>(ybuf, st);
    gn_apply_kernel<<<65536, 256>>>(ybuf, st, gn_g, gn_b, out);
}

// round 13
// speedup vs baseline: 1.7704x; 1.0525x over previous
#include <cuda_runtime.h>
#include <cuda_bf16.h>
#include <cstdint>

#define NB 4

// ------------------------- static scratch buffers --------------------------
static __device__ float g_up5 [4u * 256u * 32u * 32u];
static __device__ float g_off5[4u * 256u * 32u * 32u];
static __device__ float g_om5 [4u * 216u * 32u * 32u];
static __device__ float g_col [4u * 2304u * 64u * 64u];
static __device__ float g_al5 [4u * 256u * 32u * 32u];
static __device__ float g_c1b [4u * 256u * 32u * 32u];
static __device__ float g_up4 [4u * 256u * 64u * 64u];
static __device__ float g_off4[4u * 256u * 64u * 64u];
static __device__ float g_om4 [4u * 216u * 64u * 64u];
static __device__ float g_al4 [4u * 256u * 64u * 64u];
static __device__ float g_f2  [4u * 512u * 128u * 128u];
static __device__ float g_mm  [4u * 2u * 128u * 128u];
static __device__ float g_sab [4u * 128u * 128u];
static __device__ float g_y   [4u * 256u * 128u * 128u];
static __device__ float g_st  [256];
// pre-split weights: [hi(256*K) | lo(256*K)] bf16, M zero-padded to 256
static __device__ __align__(16) __nv_bfloat16 g_wp[5767168];
#define WP_OFF5 0u
#define WP_OM5  262144u
#define WP_DCN5 1441792u
#define WP_C1   2621440u
#define WP_OFF4 2883584u
#define WP_OM4  3145728u
#define WP_DCN4 4325376u
#define WP_SEM  5505024u

__device__ __forceinline__ uint32_t smem_to_u32(const void* p) {
    uint32_t a;
    asm("{ .reg .u64 t; cvta.to.shared.u64 t, %1; cvt.u32.u64 %0, t; }"
        : "=r"(a) : "l"(p));
    return a;
}

// ---------------------------------------------------------------------------
// Weight prep: W[M][K] fp32 -> out[0..256*K) = hi bf16, out[256*K..) = lo bf16
// ---------------------------------------------------------------------------
__global__ __launch_bounds__(256)
void prep_w_kernel(const float* __restrict__ W, __nv_bfloat16* __restrict__ out,
                   int M, int K)
{
    int idx = blockIdx.x * 256 + threadIdx.x;
    if (idx >= 256 * K) return;
    int m = idx / K, k = idx - m * K;
    float v = (m < M) ? W[(size_t)m * K + k] : 0.f;
    __nv_bfloat16 hi = __float2bfloat16(v);
    __nv_bfloat16 lo = __float2bfloat16(v - __bfloat162float(hi));
    out[idx] = hi;
    out[(size_t)256 * K + idx] = lo;
}

// X loader modes: 0 plain [K][N], 1 concat(+scale), 2 im2col3x3 pad1, 3 (1+sa)
template<int MODE>
__device__ __forceinline__ float loadX(const float* __restrict__ X0,
                                       const float* __restrict__ X1,
                                       const float* __restrict__ sa,
                                       int b, int k, int p,
                                       int K, int N, int Csplit, float scale1,
                                       int Hin, int Win)
{
    if (MODE == 0) return X0[((size_t)b * K + k) * N + p];
    else if (MODE == 1) {
        if (k < Csplit) return X0[((size_t)b * Csplit + k) * N + p];
        return scale1 * X1[((size_t)b * (K - Csplit) + (k - Csplit)) * N + p];
    } else if (MODE == 2) {
        int cin = k / 9, t = k - cin * 9;
        int hh = p / Win + (t / 3) - 1;
        int ww = (p - (p / Win) * Win) + (t - (t / 3) * 3) - 1;
        if ((unsigned)hh < (unsigned)Hin && (unsigned)ww < (unsigned)Win)
            return X0[(((size_t)b * (K / 9) + cin) * Hin + hh) * Win + ww];
        return 0.f;
    } else return X0[((size_t)b * K + k) * N + p] * (1.f + sa[(size_t)b * N + p]);
}

__device__ __forceinline__ void mma_bf16(float* c, const unsigned* a, const unsigned* b)
{
    asm volatile(
        "mma.sync.aligned.m16n8k16.row.col.f32.bf16.bf16.f32 "
        "{%0,%1,%2,%3}, {%4,%5,%6,%7}, {%8,%9}, {%0,%1,%2,%3};"
        : "+f"(c[0]), "+f"(c[1]), "+f"(c[2]), "+f"(c[3])
        : "r"(a[0]), "r"(a[1]), "r"(a[2]), "r"(a[3]), "r"(b[0]), "r"(b[1]));
}
#define LDSM_X4(R, addr) \
    asm volatile("ldmatrix.sync.aligned.m8n8.x4.shared.b16 {%0,%1,%2,%3}, [%4];" \
        : "=r"((R)[0]), "=r"((R)[1]), "=r"((R)[2]), "=r"((R)[3]) : "r"(addr))

__device__ __forceinline__ unsigned bf2(__nv_bfloat16 a, __nv_bfloat16 b)
{
    return (unsigned)__bfloat16_as_ushort(a) | ((unsigned)__bfloat16_as_ushort(b) << 16);
}

// Swizzled row/unit -> byte offset within a tile plane (rows of 80 B = 5x16B
// units, 4 data units + 1 pad; unit index XORed with (row>>3)&3 so the four
// 8-row-congruent lanes that share a bank get distinct banks).
__device__ __forceinline__ uint32_t swz(int row, int unit)
{
    return (uint32_t)(row * 80 + ((unit ^ ((row >> 3) & 3)) << 4));
}

// ---------------------------------------------------------------------------
// mma.sync bf16 split GEMM, pipelined + conflict-free swizzled smem:
//  - A (pre-split weights) via cp.async, double-buffered
//  - X prefetched to regs during compute, stored to the *other* X buffer
//    -> single __syncthreads per chunk
//  - all fragments via ldmatrix.x4; 80B rows, XOR-swizzled 16B units
// Block 128(M) x BN(N), BK=32, 256 thr (8 warps = 4M x 2N).
// acc += Ah*Xh + Ah*Xl + Al*Xh  (fp32 accum; error-free to ~2^-16).
// SMEM: A 2buf*2plane*10240 = 40960; X 2buf*2plane*(BN*80).
// ---------------------------------------------------------------------------
template<int MODE, int BN>
__global__ __launch_bounds__(256, 2)
void gemm_mma_kernel(const __nv_bfloat16* __restrict__ Wp,
                     const float* __restrict__ X0, const float* __restrict__ X1,
                     const float* __restrict__ bias, const float* __restrict__ sa,
                     float* __restrict__ out,
                     int M, int K, int N, int Csplit, float scale1,
                     int Hin, int Win, int relu)
{
    constexpr int WN  = BN / 2;        // warp N tile
    constexpr int JT  = BN / 16;       // 8x8-col mma tiles per warp (j loop)
    constexpr int JP  = JT / 2;        // ldmatrix.x4 groups (16 cols each)
    constexpr int KPT = BN / 8;        // k elems per thread in X fill
    constexpr int RR  = KPT / 2;
    constexpr int A_PLANE = 10240, A_BUF = 20480;
    constexpr int X_PLANE = BN * 80, X_BUF = 2 * X_PLANE, X_BASE = 40960;

    extern __shared__ char smem[];
    const uint32_t su = smem_to_u32(smem);

    const int tid = threadIdx.x;
    const int wid = tid >> 5, lane = tid & 31;
    const int warp_m = wid & 3;
    const int warp_n = wid >> 2;
    const int lq = lane >> 2;
    const int lr = lane & 3;
    const int m0 = blockIdx.y * 128;
    const int n0 = blockIdx.x * BN;
    const int b  = blockIdx.z;
    const int NC = K / 32;
    const size_t loStride = (size_t)256 * K;

    float acc[2][JT][4];
#pragma unroll
    for (int i = 0; i < 2; i++)
#pragma unroll
        for (int j = 0; j < JT; j++)
#pragma unroll
            for (int q = 0; q < 4; q++) acc[i][j][q] = 0.f;

    const int ar = lane & 7, aj = lane >> 3;

    auto prefA = [&](int c, int buf) {
        uint32_t sb = su + (uint32_t)buf * A_BUF;
#pragma unroll
        for (int r = 0; r < 4; r++) {
            int idx = tid + r * 256;
            int plane = idx >> 9;
            int rem = idx & 511;
            int m = rem & 127, q = rem >> 7;
            const __nv_bfloat16* g = Wp + (size_t)plane * loStride
                                   + (size_t)(m0 + m) * K + c * 32 + q * 8;
            uint32_t d = sb + (uint32_t)plane * A_PLANE + swz(m, q);
            asm volatile("cp.async.cg.shared.global [%0], [%1], 16;" :: "r"(d), "l"(g));
        }
        asm volatile("cp.async.commit_group;");
    };

    const int xn = tid % BN, xkh = tid / BN;
    auto prefX = [&](int c, float* xv) {
#pragma unroll
        for (int rr = 0; rr < RR; rr++) {
            int k = c * 32 + xkh * KPT + rr * 2;
            xv[rr * 2]     = loadX<MODE>(X0, X1, sa, b, k,     n0 + xn, K, N, Csplit, scale1, Hin, Win);
            xv[rr * 2 + 1] = loadX<MODE>(X0, X1, sa, b, k + 1, n0 + xn, K, N, Csplit, scale1, Hin, Win);
        }
    };
    auto storeX = [&](const float* xv, int buf) {
        unsigned* Xh32 = (unsigned*)(smem + X_BASE + buf * X_BUF);
        unsigned* Xl32 = (unsigned*)(smem + X_BASE + buf * X_BUF + X_PLANE);
        int swzbase = (xn >> 3) & 3;
#pragma unroll
        for (int rr = 0; rr < RR; rr++) {
            int kl = xkh * KPT + rr * 2;       // local k (even)
            float v0 = xv[rr * 2], v1 = xv[rr * 2 + 1];
            __nv_bfloat16 h0 = __float2bfloat16(v0), h1 = __float2bfloat16(v1);
            __nv_bfloat16 l0 = __float2bfloat16(v0 - __bfloat162float(h0));
            __nv_bfloat16 l1 = __float2bfloat16(v1 - __bfloat162float(h1));
            int u = kl >> 3;
            int idx32 = xn * 20 + (((u ^ swzbase) << 2) | ((kl >> 1) & 3));
            Xh32[idx32] = bf2(h0, h1);
            Xl32[idx32] = bf2(l0, l1);
        }
    };

    auto compute = [&](int buf) {
        uint32_t aB = su + (uint32_t)buf * A_BUF;
        uint32_t xB = su + X_BASE + (uint32_t)buf * X_BUF;
#pragma unroll
        for (int ks = 0; ks < 2; ks++) {
            unsigned ah[2][4], al[2][4];
#pragma unroll
            for (int i = 0; i < 2; i++) {
                int arow = warp_m * 32 + i * 16 + ar + (aj & 1) * 8;
                int aunit = (aj >> 1) + ks * 2;
                LDSM_X4(ah[i], aB + swz(arow, aunit));
                LDSM_X4(al[i], aB + A_PLANE + swz(arow, aunit));
            }
#pragma unroll
            for (int jp = 0; jp < JP; jp++) {
                int brow = warp_n * WN + jp * 16 + (aj >> 1) * 8 + ar;
                int bunit = (aj & 1) + ks * 2;
                unsigned bh[4], bl[4];
                LDSM_X4(bh, xB + swz(brow, bunit));
                LDSM_X4(bl, xB + X_PLANE + swz(brow, bunit));
#pragma unroll
                for (int jo = 0; jo < 2; jo++) {
                    int j = jp * 2 + jo;
#pragma unroll
                    for (int i = 0; i < 2; i++) {
                        mma_bf16(acc[i][j], ah[i], bh + jo * 2);
                        mma_bf16(acc[i][j], ah[i], bl + jo * 2);
                        mma_bf16(acc[i][j], al[i], bh + jo * 2);
                    }
                }
            }
        }
    };

    float xv[KPT];
    prefA(0, 0);
    prefX(0, xv);
    storeX(xv, 0);
    asm volatile("cp.async.wait_group 0;");
    __syncthreads();

    for (int c = 0; c < NC; c++) {
        int cur = c & 1;
        bool more = (c + 1 < NC);
        if (more) {
            prefA(c + 1, cur ^ 1);
            prefX(c + 1, xv);
        }
        compute(cur);
        if (more) {
            storeX(xv, cur ^ 1);
            asm volatile("cp.async.wait_group 0;");
        }
        __syncthreads();
    }

    // ---- epilogue ----
#pragma unroll
    for (int i = 0; i < 2; i++) {
        int row0 = m0 + warp_m * 32 + i * 16 + lq;
        int row1 = row0 + 8;
        float bv0 = 0.f, bv1 = 0.f;
        if (bias) {
            if (row0 < M) bv0 = bias[row0];
            if (row1 < M) bv1 = bias[row1];
        }
#pragma unroll
        for (int j = 0; j < JT; j++) {
            int col = n0 + warp_n * WN + j * 8 + lr * 2;
            float2 o0, o1;
            o0.x = acc[i][j][0] + bv0; o0.y = acc[i][j][1] + bv0;
            o1.x = acc[i][j][2] + bv1; o1.y = acc[i][j][3] + bv1;
            if (relu) {
                o0.x = fmaxf(o0.x, 0.f); o0.y = fmaxf(o0.y, 0.f);
                o1.x = fmaxf(o1.x, 0.f); o1.y = fmaxf(o1.y, 0.f);
            }
            if (row0 < M)
                *(float2*)&out[((size_t)b * M + row0) * N + col] = o0;
            if (row1 < M)
                *(float2*)&out[((size_t)b * M + row1) * N + col] = o1;
        }
    }
}

#define SMEM128 81920
#define SMEM64  61440

// ------------------------- elementwise kernels -----------------------------
__global__ __launch_bounds__(256)
void upsample2x_kernel(const float* __restrict__ src0,
                       const float* __restrict__ src1,
                       int Csplit, int C, int Hin, int Win,
                       float* __restrict__ dst)
{
    const int Hout = Hin * 2, Wout = Win * 2;
    const long total = (long)NB * C * Hout * Wout;
    long idx = (long)blockIdx.x * blockDim.x + threadIdx.x;
    if (idx >= total) return;
    int x = (int)(idx % Wout);
    int y = (int)((idx / Wout) % Hout);
    int c = (int)((idx / ((long)Wout * Hout)) % C);
    int b = (int)(idx / ((long)Wout * Hout * C));
    float sy = y * 0.5f - 0.25f, sx = x * 0.5f - 0.25f;
    float y0f = floorf(sy), x0f = floorf(sx);
    float fy = sy - y0f, fx = sx - x0f;
    int y0 = (int)y0f, x0 = (int)x0f;
    int y0c = min(max(y0, 0), Hin - 1), y1c = min(max(y0 + 1, 0), Hin - 1);
    int x0c = min(max(x0, 0), Win - 1), x1c = min(max(x0 + 1, 0), Win - 1);
    const float* s = (c < Csplit)
        ? src0 + (size_t)(b * Csplit + c) * Hin * Win
        : src1 + (size_t)(b * (C - Csplit) + (c - Csplit)) * Hin * Win;
    float v00 = s[y0c * Win + x0c], v01 = s[y0c * Win + x1c];
    float v10 = s[y1c * Win + x0c], v11 = s[y1c * Win + x1c];
    dst[idx] = (1.f - fy) * ((1.f - fx) * v00 + fx * v01)
             +         fy * ((1.f - fx) * v10 + fx * v11);
}

__global__ __launch_bounds__(256)
void dcn_sample_kernel(const float* __restrict__ x, const float* __restrict__ om,
                       float* __restrict__ col, int H, int W)
{
    const int HW = H * W;
    const int total = NB * 72 * HW;
    int idx = blockIdx.x * blockDim.x + threadIdx.x;
    if (idx >= total) return;
    int p = idx % HW, gk = (idx / HW) % 72, b = idx / (72 * HW);
    int g = gk / 9, k = gk - g * 9;
    int h = p / W, w = p - h * W;
    float offy = om[((size_t)b * 216 +       gk) * HW + p];
    float offx = om[((size_t)b * 216 + 72 +  gk) * HW + p];
    float mraw = om[((size_t)b * 216 + 144 + gk) * HW + p];
    float msk = 1.f / (1.f + expf(-mraw));
    float yy = (float)h + (float)(k / 3 - 1) + offy;
    float xx = (float)w + (float)(k % 3 - 1) + offx;
    yy = fminf(fmaxf(yy, -1.0e6f), 1.0e6f);
    xx = fminf(fmaxf(xx, -1.0e6f), 1.0e6f);
    float y0f = floorf(yy), x0f = floorf(xx);
    int y0 = (int)y0f, x0 = (int)x0f;
    float fy = yy - y0f, fx = xx - x0f;
    bool vy0 = (y0 >= 0) && (y0 < H), vy1 = (y0 + 1 >= 0) && (y0 + 1 < H);
    bool vx0 = (x0 >= 0) && (x0 < W), vx1 = (x0 + 1 >= 0) && (x0 + 1 < W);
    int cy0 = min(max(y0, 0), H - 1), cy1 = min(max(y0 + 1, 0), H - 1);
    int cx0 = min(max(x0, 0), W - 1), cx1 = min(max(x0 + 1, 0), W - 1);
    float w00 = (vy0 && vx0) ? (1.f - fy) * (1.f - fx) * msk : 0.f;
    float w01 = (vy0 && vx1) ? (1.f - fy) * fx * msk : 0.f;
    float w10 = (vy1 && vx0) ? fy * (1.f - fx) * msk : 0.f;
    float w11 = (vy1 && vx1) ? fy * fx * msk : 0.f;
    int i00 = cy0 * W + cx0, i01 = cy0 * W + cx1;
    int i10 = cy1 * W + cx0, i11 = cy1 * W + cx1;
    const float* xb = x + (size_t)(b * 256 + g * 32) * HW;
    float* cb = col + ((size_t)b * 2304 + (size_t)(g * 32) * 9 + k) * HW + p;
#pragma unroll 4
    for (int c = 0; c < 32; c++) {
        const float* xc = xb + (size_t)c * HW;
        float v = w00 * xc[i00] + w01 * xc[i01] + w10 * xc[i10] + w11 * xc[i11];
        cb[(size_t)c * 9 * HW] = v;
    }
}

__global__ __launch_bounds__(256)
void meanmax_kernel(const float* __restrict__ f2, float* __restrict__ mm)
{
    int p = blockIdx.x * blockDim.x + threadIdx.x;
    int b = blockIdx.y;
    if (p >= 16384) return;
    const float* base = f2 + (size_t)b * 512 * 16384 + p;
    float s = 0.f, mx = -3.402823466e38f;
    for (int c = 0; c < 512; c++) {
        float v = base[(size_t)c * 16384];
        s += v;
        mx = fmaxf(mx, v);
    }
    mm[((size_t)b * 2 + 0) * 16384 + p] = s * (1.f / 512.f);
    mm[((size_t)b * 2 + 1) * 16384 + p] = mx;
}

__global__ __launch_bounds__(256)
void sa_kernel(const float* __restrict__ mm, const float* __restrict__ wsa,
               const float* __restrict__ bng, const float* __restrict__ bnb,
               const float* __restrict__ bnm, const float* __restrict__ bnv,
               float* __restrict__ sa)
{
    int p = blockIdx.x * blockDim.x + threadIdx.x;
    int b = blockIdx.y;
    if (p >= 16384) return;
    int y = p >> 7, x = p & 127;
    float acc = 0.f;
#pragma unroll
    for (int ic = 0; ic < 2; ic++) {
        const float* src = mm + ((size_t)b * 2 + ic) * 16384;
        const float* wk = wsa + ic * 49;
#pragma unroll
        for (int ky = 0; ky < 7; ky++) {
            int yy = y + ky - 3;
            if ((unsigned)yy >= 128u) continue;
#pragma unroll
            for (int kx = 0; kx < 7; kx++) {
                int xx = x + kx - 3;
                if ((unsigned)xx >= 128u) continue;
                acc += src[yy * 128 + xx] * wk[ky * 7 + kx];
            }
        }
    }
    float a = (acc - bnm[0]) * rsqrtf(bnv[0] + 1e-5f) * bng[0] + bnb[0];
    sa[(size_t)b * 16384 + p] = 1.f / (1.f + expf(-a));
}

__global__ __launch_bounds__(256)
void gn_reduce_kernel(const float* __restrict__ y, float* __restrict__ stats)
{
    const int bg = blockIdx.x;
    const float* base = y + (size_t)bg * 8 * 16384;
    float s = 0.f, sq = 0.f;
    for (int i = threadIdx.x; i < 8 * 16384; i += 256) {
        float v = base[i];
        s += v;
        sq += v * v;
    }
    __shared__ float ss[256], ssq[256];
    ss[threadIdx.x] = s;
    ssq[threadIdx.x] = sq;
    __syncthreads();
    for (int st = 128; st > 0; st >>= 1) {
        if (threadIdx.x < st) {
            ss[threadIdx.x] += ss[threadIdx.x + st];
            ssq[threadIdx.x] += ssq[threadIdx.x + st];
        }
        __syncthreads();
    }
    if (threadIdx.x == 0) {
        const float inv = 1.f / (8.f * 16384.f);
        float mean = ss[0] * inv;
        float var = ssq[0] * inv - mean * mean;
        stats[bg * 2 + 0] = mean;
        stats[bg * 2 + 1] = rsqrtf(var + 1e-5f);
    }
}

__global__ __launch_bounds__(256)
void gn_apply_kernel(const float* __restrict__ y, const float* __restrict__ stats,
                     const float* __restrict__ gg, const float* __restrict__ gb,
                     float* __restrict__ out)
{
    size_t idx = (size_t)blockIdx.x * blockDim.x + threadIdx.x;
    if (idx >= (size_t)16777216) return;
    int c = (int)((idx >> 14) & 255);
    int b = (int)(idx >> 22);
    int g = c >> 3;
    float mean = stats[(b * 32 + g) * 2 + 0];
    float rstd = stats[(b * 32 + g) * 2 + 1];
    out[idx] = (y[idx] - mean) * rstd * gg[c] + gb[c];
}

// ------------------------------ host ---------------------------------------
static void* symaddr(const void* sym)
{
    void* p = nullptr;
    cudaGetSymbolAddress(&p, sym);
    return p;
}

extern "C" void kernel_launch(void* const* d_in, const int* in_sizes, int n_in,
                              void* d_out, int out_size)
{
    (void)in_sizes; (void)n_in; (void)out_size;
    const float* feat_3 = (const float*)d_in[1];
    const float* feat_4 = (const float*)d_in[2];
    const float* feat_5 = (const float*)d_in[3];
    const float* w_off5 = (const float*)d_in[4];
    const float* w_om5  = (const float*)d_in[5];
    const float* b_om5  = (const float*)d_in[6];
    const float* w_dcn5 = (const float*)d_in[7];
    const float* b_dcn5 = (const float*)d_in[8];
    const float* w_c1   = (const float*)d_in[9];
    const float* w_off4 = (const float*)d_in[10];
    const float* w_om4  = (const float*)d_in[11];
    const float* b_om4  = (const float*)d_in[12];
    const float* w_dcn4 = (const float*)d_in[13];
    const float* b_dcn4 = (const float*)d_in[14];
    const float* w_sa   = (const float*)d_in[15];
    const float* bn_g   = (const float*)d_in[16];
    const float* bn_b   = (const float*)d_in[17];
    const float* bn_m   = (const float*)d_in[18];
    const float* bn_v   = (const float*)d_in[19];
    const float* w_sem  = (const float*)d_in[20];
    const float* gn_g   = (const float*)d_in[21];
    const float* gn_b   = (const float*)d_in[22];
    float* out = (float*)d_out;

    float* up5  = (float*)symaddr(g_up5);
    float* off5 = (float*)symaddr(g_off5);
    float* om5  = (float*)symaddr(g_om5);
    float* col  = (float*)symaddr(g_col);
    float* al5  = (float*)symaddr(g_al5);
    float* c1b  = (float*)symaddr(g_c1b);
    float* up4  = (float*)symaddr(g_up4);
    float* off4 = (float*)symaddr(g_off4);
    float* om4  = (float*)symaddr(g_om4);
    float* al4  = (float*)symaddr(g_al4);
    float* f2   = (float*)symaddr(g_f2);
    float* mm   = (float*)symaddr(g_mm);
    float* sab  = (float*)symaddr(g_sab);
    float* ybuf = (float*)symaddr(g_y);
    float* st   = (float*)symaddr(g_st);
    __nv_bfloat16* wp = (__nv_bfloat16*)symaddr(g_wp);

    cudaFuncSetAttribute(gemm_mma_kernel<0, 64>,  cudaFuncAttributeMaxDynamicSharedMemorySize, SMEM64);
    cudaFuncSetAttribute(gemm_mma_kernel<1, 64>,  cudaFuncAttributeMaxDynamicSharedMemorySize, SMEM64);
    cudaFuncSetAttribute(gemm_mma_kernel<2, 64>,  cudaFuncAttributeMaxDynamicSharedMemorySize, SMEM64);
    cudaFuncSetAttribute(gemm_mma_kernel<0, 128>, cudaFuncAttributeMaxDynamicSharedMemorySize, SMEM128);
    cudaFuncSetAttribute(gemm_mma_kernel<1, 128>, cudaFuncAttributeMaxDynamicSharedMemorySize, SMEM128);
    cudaFuncSetAttribute(gemm_mma_kernel<2, 128>, cudaFuncAttributeMaxDynamicSharedMemorySize, SMEM128);
    cudaFuncSetAttribute(gemm_mma_kernel<3, 128>, cudaFuncAttributeMaxDynamicSharedMemorySize, SMEM128);

    // weight prep (graph-capturable, cheap)
    prep_w_kernel<<<512, 256>>>(w_off5, wp + WP_OFF5, 256, 512);
    prep_w_kernel<<<2304, 256>>>(w_om5,  wp + WP_OM5, 216, 2304);
    prep_w_kernel<<<2304, 256>>>(w_dcn5, wp + WP_DCN5, 256, 2304);
    prep_w_kernel<<<512, 256>>>(w_c1,   wp + WP_C1, 256, 512);
    prep_w_kernel<<<512, 256>>>(w_off4, wp + WP_OFF4, 256, 512);
    prep_w_kernel<<<2304, 256>>>(w_om4,  wp + WP_OM4, 216, 2304);
    prep_w_kernel<<<2304, 256>>>(w_dcn4, wp + WP_DCN4, 256, 2304);
    prep_w_kernel<<<512, 256>>>(w_sem,  wp + WP_SEM, 256, 512);

    // ----- level 5 (16 -> 32), N=1024, BN=64 to fill the chip -----
    upsample2x_kernel<<<(4 * 256 * 1024 + 255) / 256, 256>>>(
        feat_5, feat_5, 256, 256, 16, 16, up5);
    gemm_mma_kernel<1, 64><<<dim3(16, 2, NB), 256, SMEM64>>>(
        wp + WP_OFF5, feat_4, up5, nullptr, nullptr, off5,
        256, 512, 1024, 256, 2.0f, 0, 0, 0);
    gemm_mma_kernel<2, 64><<<dim3(16, 2, NB), 256, SMEM64>>>(
        wp + WP_OM5, off5, nullptr, b_om5, nullptr, om5,
        216, 2304, 1024, 0, 0.f, 32, 32, 0);
    dcn_sample_kernel<<<(NB * 72 * 1024 + 255) / 256, 256>>>(up5, om5, col, 32, 32);
    gemm_mma_kernel<0, 64><<<dim3(16, 2, NB), 256, SMEM64>>>(
        wp + WP_DCN5, col, nullptr, b_dcn5, nullptr, al5,
        256, 2304, 1024, 0, 0.f, 0, 0, 1);
    gemm_mma_kernel<1, 64><<<dim3(16, 2, NB), 256, SMEM64>>>(
        wp + WP_C1, al5, feat_4, nullptr, nullptr, c1b,
        256, 512, 1024, 256, 1.0f, 0, 0, 0);

    // ----- level 4 (32 -> 64), N=4096, BN=128 -----
    upsample2x_kernel<<<(4 * 256 * 4096 + 255) / 256, 256>>>(
        c1b, c1b, 256, 256, 32, 32, up4);
    gemm_mma_kernel<1, 128><<<dim3(32, 2, NB), 256, SMEM128>>>(
        wp + WP_OFF4, feat_3, up4, nullptr, nullptr, off4,
        256, 512, 4096, 256, 2.0f, 0, 0, 0);
    gemm_mma_kernel<2, 128><<<dim3(32, 2, NB), 256, SMEM128>>>(
        wp + WP_OM4, off4, nullptr, b_om4, nullptr, om4,
        216, 2304, 4096, 0, 0.f, 64, 64, 0);
    dcn_sample_kernel<<<(NB * 72 * 4096 + 255) / 256, 256>>>(up4, om4, col, 64, 64);
    gemm_mma_kernel<0, 128><<<dim3(32, 2, NB), 256, SMEM128>>>(
        wp + WP_DCN4, col, nullptr, b_dcn4, nullptr, al4,
        256, 2304, 4096, 0, 0.f, 0, 0, 1);

    // ----- feat_2 + SEM -----
    upsample2x_kernel<<<(unsigned)((4L * 512 * 16384 + 255) / 256), 256>>>(
        al4, feat_3, 256, 512, 64, 64, f2);
    meanmax_kernel<<<dim3(64, NB), 256>>>(f2, mm);
    sa_kernel<<<dim3(64, NB), 256>>>(mm, w_sa, bn_g, bn_b, bn_m, bn_v, sab);
    gemm_mma_kernel<3, 128><<<dim3(128, 2, NB), 256, SMEM128>>>(
        wp + WP_SEM, f2, nullptr, nullptr, sab, ybuf,
        256, 512, 16384, 0, 0.f, 0, 0, 0);
    gn_reduce_kernel<<<128, 256>>>(ybuf, st);
    gn_apply_kernel<<<65536, 256>>>(ybuf, st, gn_g, gn_b, out);
}